// round 1
// baseline (speedup 1.0000x reference)
#include <cuda_runtime.h>
#include <math.h>

#define BSZ  8
#define SEQL 1024
#define EMB  1024
#define NH   16
#define HD   64
#define MTOT (BSZ * SEQL)   // 8192

// ---------------- scratch (device globals; no allocations allowed) ----------
__device__ float g_q[MTOT * EMB];
__device__ float g_k[MTOT * EMB];
__device__ float g_v[MTOT * EMB];
__device__ float g_attn[MTOT * EMB];
__device__ float g_cq[SEQL * 32];
__device__ float g_sq[SEQL * 32];
__device__ float g_ck[SEQL * 32];
__device__ float g_sk[SEQL * 32];

// ---------------- xpos cos/sin * scale tables --------------------------------
// scale[t,i] = s_i ^ (pos_t / SCALE_BASE), s_i = (2i + 0.4*D)/(1.4*D),
// pos_t = t - SEQL/2, SCALE_BASE = EMB. theta = t * 10000^{-i/(D/2)}.
__global__ void build_tables_kernel() {
    int idx = blockIdx.x * blockDim.x + threadIdx.x;
    if (idx >= SEQL * 32) return;
    int t = idx >> 5;
    int i = idx & 31;
    float s_i   = (2.0f * (float)i + 0.4f * (float)HD) / (1.4f * (float)HD);
    float pos   = (float)t - (float)(SEQL / 2);
    float scale = powf(s_i, pos / (float)EMB);
    float invf  = powf(10000.0f, -(float)i / (float)(HD / 2));
    float sn, cs;
    sincosf((float)t * invf, &sn, &cs);
    g_cq[idx] = cs * scale;
    g_sq[idx] = sn * scale;
    g_ck[idx] = cs / scale;
    g_sk[idx] = sn / scale;
}

// ---------------- xpos rotation (in place) -----------------------------------
// x: [MTOT, EMB]. pair index pc = h*32 + i -> cols (2*pc, 2*pc+1) = (h*64+2i, +1)
__global__ void xpos_apply_kernel(float* __restrict__ x,
                                  const float* __restrict__ ct,
                                  const float* __restrict__ st) {
    int idx = blockIdx.x * blockDim.x + threadIdx.x;  // pair index, total MTOT*512
    int row = idx >> 9;
    int pc  = idx & 511;
    int t   = row & (SEQL - 1);
    int i   = pc & 31;
    float c = ct[(t << 5) + i];
    float s = st[(t << 5) + i];
    float2* p = (float2*)(x + ((size_t)row << 10)) + pc;
    float2 v = *p;
    float2 r;
    r.x = v.x * c - v.y * s;
    r.y = v.y * c + v.x * s;
    *p = r;
}

// ---------------- C = alpha * (A @ W^T + bias) -------------------------------
// A: [M,K] row-major, W: [N,K] row-major. Tiles 64x64x16, 256 thr, 4x4/thread.
__global__ __launch_bounds__(256) void gemm_nt_bias_kernel(
    const float* __restrict__ A, const float* __restrict__ W,
    const float* __restrict__ bias, float* __restrict__ C,
    int M, int N, int K, float alpha)
{
    __shared__ float As[16][64];  // [k][m] transposed
    __shared__ float Ws[16][64];  // [k][n] transposed

    const int tx = threadIdx.x & 15;
    const int ty = threadIdx.x >> 4;
    const int m0 = blockIdx.y << 6;
    const int n0 = blockIdx.x << 6;
    const int lrow = threadIdx.x >> 2;        // 0..63
    const int lk   = (threadIdx.x & 3) << 2;  // 0,4,8,12

    const float* Ap = A + (size_t)(m0 + lrow) * K + lk;
    const float* Wp = W + (size_t)(n0 + lrow) * K + lk;

    float acc[4][4] = {};

    for (int k0 = 0; k0 < K; k0 += 16) {
        float4 av = *(const float4*)(Ap + k0);
        float4 wv = *(const float4*)(Wp + k0);
        As[lk + 0][lrow] = av.x; As[lk + 1][lrow] = av.y;
        As[lk + 2][lrow] = av.z; As[lk + 3][lrow] = av.w;
        Ws[lk + 0][lrow] = wv.x; Ws[lk + 1][lrow] = wv.y;
        Ws[lk + 2][lrow] = wv.z; Ws[lk + 3][lrow] = wv.w;
        __syncthreads();
#pragma unroll
        for (int kk = 0; kk < 16; kk++) {
            float4 a4 = *(const float4*)&As[kk][ty << 2];
            float4 b4 = *(const float4*)&Ws[kk][tx << 2];
            float a[4] = {a4.x, a4.y, a4.z, a4.w};
            float b[4] = {b4.x, b4.y, b4.z, b4.w};
#pragma unroll
            for (int i = 0; i < 4; i++)
#pragma unroll
                for (int j = 0; j < 4; j++)
                    acc[i][j] = fmaf(a[i], b[j], acc[i][j]);
        }
        __syncthreads();
    }

#pragma unroll
    for (int i = 0; i < 4; i++) {
        int r = m0 + (ty << 2) + i;
        int c = n0 + (tx << 2);
        float4 bv = *(const float4*)(bias + c);
        float4 w;
        w.x = alpha * (acc[i][0] + bv.x);
        w.y = alpha * (acc[i][1] + bv.y);
        w.z = alpha * (acc[i][2] + bv.z);
        w.w = alpha * (acc[i][3] + bv.w);
        *(float4*)(C + (size_t)r * N + c) = w;
    }
}

// ---------------- flash attention, per (b,h, 64-query tile) ------------------
// Q,K,V,O: [MTOT, EMB]; head h occupies cols [h*64, h*64+64).
__global__ __launch_bounds__(256) void attn_kernel(
    const float* __restrict__ Q, const float* __restrict__ K,
    const float* __restrict__ V, float* __restrict__ O)
{
    __shared__ float Qst[64][64];  // [d][r]
    __shared__ float KP[64][64];   // K^T tile [d][c], aliased as P^T [c][r]
    __shared__ float Vs[64][64];   // [c][d]

    const int bh = blockIdx.x;
    const int qt = blockIdx.y;
    const int b  = bh >> 4;
    const int h  = bh & 15;

    const float* qb = Q + ((size_t)(b * SEQL) + qt * 64) * EMB + h * HD;
    const float* kb = K + (size_t)(b * SEQL) * EMB + h * HD;
    const float* vb = V + (size_t)(b * SEQL) * EMB + h * HD;
    float*       ob = O + ((size_t)(b * SEQL) + qt * 64) * EMB + h * HD;

    const int tx = threadIdx.x & 15;
    const int ty = threadIdx.x >> 4;

    // load Q tile transposed: Qst[d][r]
#pragma unroll
    for (int it = 0; it < 4; it++) {
        int f  = threadIdx.x + (it << 8);
        int r  = f >> 4;
        int d4 = (f & 15) << 2;
        float4 v = *(const float4*)(qb + (size_t)r * EMB + d4);
        Qst[d4 + 0][r] = v.x; Qst[d4 + 1][r] = v.y;
        Qst[d4 + 2][r] = v.z; Qst[d4 + 3][r] = v.w;
    }

    float o[4][4] = {};
    float m_run[4] = {-INFINITY, -INFINITY, -INFINITY, -INFINITY};
    float l_run[4] = {};

    for (int kt = 0; kt < SEQL / 64; kt++) {
        __syncthreads();  // previous PV done before overwriting KP / Vs
#pragma unroll
        for (int it = 0; it < 4; it++) {
            int f  = threadIdx.x + (it << 8);
            int r  = f >> 4;
            int d4 = (f & 15) << 2;
            float4 kv = *(const float4*)(kb + (size_t)(kt * 64 + r) * EMB + d4);
            KP[d4 + 0][r] = kv.x; KP[d4 + 1][r] = kv.y;
            KP[d4 + 2][r] = kv.z; KP[d4 + 3][r] = kv.w;
            float4 vv = *(const float4*)(vb + (size_t)(kt * 64 + r) * EMB + d4);
            *(float4*)&Vs[r][d4] = vv;
        }
        __syncthreads();

        // S = Q @ K^T  (s[i][j]: row ty*4+i, col tx*4+j)
        float s[4][4] = {};
#pragma unroll
        for (int dd = 0; dd < 64; dd++) {
            float4 a4 = *(const float4*)&Qst[dd][ty << 2];
            float4 b4 = *(const float4*)&KP[dd][tx << 2];
            float a[4] = {a4.x, a4.y, a4.z, a4.w};
            float bb[4] = {b4.x, b4.y, b4.z, b4.w};
#pragma unroll
            for (int i = 0; i < 4; i++)
#pragma unroll
                for (int j = 0; j < 4; j++)
                    s[i][j] = fmaf(a[i], bb[j], s[i][j]);
        }

        // online softmax: 16 threads sharing ty own one row group (lanes xor 1,2,4,8)
        float p[4][4];
#pragma unroll
        for (int i = 0; i < 4; i++) {
            float tm = fmaxf(fmaxf(s[i][0], s[i][1]), fmaxf(s[i][2], s[i][3]));
#pragma unroll
            for (int msk = 1; msk < 16; msk <<= 1)
                tm = fmaxf(tm, __shfl_xor_sync(0xffffffffu, tm, msk));
            float nm = fmaxf(m_run[i], tm);
            float al = __expf(m_run[i] - nm);
            float ts = 0.0f;
#pragma unroll
            for (int j = 0; j < 4; j++) {
                p[i][j] = __expf(s[i][j] - nm);
                ts += p[i][j];
            }
#pragma unroll
            for (int msk = 1; msk < 16; msk <<= 1)
                ts += __shfl_xor_sync(0xffffffffu, ts, msk);
            l_run[i] = l_run[i] * al + ts;
            m_run[i] = nm;
#pragma unroll
            for (int j = 0; j < 4; j++) o[i][j] *= al;
        }

        __syncthreads();  // done reading K^T from KP
        // store P transposed over KP: KP[c][r]
#pragma unroll
        for (int i = 0; i < 4; i++)
#pragma unroll
            for (int j = 0; j < 4; j++)
                KP[(tx << 2) + j][(ty << 2) + i] = p[i][j];
        __syncthreads();

        // O += P @ V  (o[i][j]: row ty*4+i, dim tx*4+j)
#pragma unroll
        for (int cc = 0; cc < 64; cc++) {
            float4 p4 = *(const float4*)&KP[cc][ty << 2];
            float4 v4 = *(const float4*)&Vs[cc][tx << 2];
            float pa[4] = {p4.x, p4.y, p4.z, p4.w};
            float va[4] = {v4.x, v4.y, v4.z, v4.w};
#pragma unroll
            for (int i = 0; i < 4; i++)
#pragma unroll
                for (int j = 0; j < 4; j++)
                    o[i][j] = fmaf(pa[i], va[j], o[i][j]);
        }
    }

#pragma unroll
    for (int i = 0; i < 4; i++) {
        float inv = 1.0f / l_run[i];
        float4 w;
        w.x = o[i][0] * inv; w.y = o[i][1] * inv;
        w.z = o[i][2] * inv; w.w = o[i][3] * inv;
        *(float4*)(ob + (size_t)((ty << 2) + i) * EMB + (tx << 2)) = w;
    }
}

// ---------------- launch ------------------------------------------------------
extern "C" void kernel_launch(void* const* d_in, const int* in_sizes, int n_in,
                              void* d_out, int out_size) {
    const float* query = (const float*)d_in[0];
    const float* key_  = (const float*)d_in[1];
    const float* value = (const float*)d_in[2];
    const float* wq = (const float*)d_in[3];
    const float* bq = (const float*)d_in[4];
    const float* wk = (const float*)d_in[5];
    const float* bk = (const float*)d_in[6];
    const float* wv = (const float*)d_in[7];
    const float* bv = (const float*)d_in[8];
    const float* wo = (const float*)d_in[9];
    const float* bo = (const float*)d_in[10];
    float* out = (float*)d_out;

    float *qp, *kp, *vp, *ap, *cq, *sq, *ck, *sk;
    cudaGetSymbolAddress((void**)&qp, g_q);
    cudaGetSymbolAddress((void**)&kp, g_k);
    cudaGetSymbolAddress((void**)&vp, g_v);
    cudaGetSymbolAddress((void**)&ap, g_attn);
    cudaGetSymbolAddress((void**)&cq, g_cq);
    cudaGetSymbolAddress((void**)&sq, g_sq);
    cudaGetSymbolAddress((void**)&ck, g_ck);
    cudaGetSymbolAddress((void**)&sk, g_sk);

    build_tables_kernel<<<(SEQL * 32 + 255) / 256, 256>>>();

    dim3 gg(EMB / 64, MTOT / 64);  // (16, 128)
    const float scaling = 0.125f;  // HD^-0.5
    gemm_nt_bias_kernel<<<gg, 256>>>(query, wq, bq, qp, MTOT, EMB, EMB, scaling);
    gemm_nt_bias_kernel<<<gg, 256>>>(key_,  wk, bk, kp, MTOT, EMB, EMB, 1.0f);
    gemm_nt_bias_kernel<<<gg, 256>>>(value, wv, bv, vp, MTOT, EMB, EMB, 1.0f);

    int npair = MTOT * (EMB / 2);
    xpos_apply_kernel<<<npair / 256, 256>>>(qp, cq, sq);
    xpos_apply_kernel<<<npair / 256, 256>>>(kp, ck, sk);

    attn_kernel<<<dim3(BSZ * NH, SEQL / 64), 256>>>(qp, kp, vp, ap);

    gemm_nt_bias_kernel<<<gg, 256>>>(ap, wo, bo, out, MTOT, EMB, EMB, 1.0f);
}

// round 2
// speedup vs baseline: 1.3305x; 1.3305x over previous
#include <cuda_runtime.h>
#include <math.h>

#define BSZ  8
#define SEQL 1024
#define EMB  1024
#define NH   16
#define HD   64
#define MTOT (BSZ * SEQL)   // 8192

// ---------------- scratch (device globals; no allocations allowed) ----------
__device__ float g_q[MTOT * EMB];
__device__ float g_k[MTOT * EMB];
__device__ float g_v[MTOT * EMB];
__device__ float g_attn[MTOT * EMB];
__device__ float g_cq[SEQL * 32];
__device__ float g_sq[SEQL * 32];
__device__ float g_ck[SEQL * 32];
__device__ float g_sk[SEQL * 32];

// ---------------- xpos cos/sin * scale tables --------------------------------
__global__ void build_tables_kernel() {
    int idx = blockIdx.x * blockDim.x + threadIdx.x;
    if (idx >= SEQL * 32) return;
    int t = idx >> 5;
    int i = idx & 31;
    float s_i   = (2.0f * (float)i + 0.4f * (float)HD) / (1.4f * (float)HD);
    float pos   = (float)t - (float)(SEQL / 2);
    float scale = powf(s_i, pos / (float)EMB);
    float invf  = powf(10000.0f, -(float)i / (float)(HD / 2));
    float sn, cs;
    sincosf((float)t * invf, &sn, &cs);
    g_cq[idx] = cs * scale;
    g_sq[idx] = sn * scale;
    g_ck[idx] = cs / scale;
    g_sk[idx] = sn / scale;
}

// ---------------- xpos rotation (in place) -----------------------------------
__global__ void xpos_apply_kernel(float* __restrict__ x,
                                  const float* __restrict__ ct,
                                  const float* __restrict__ st) {
    int idx = blockIdx.x * blockDim.x + threadIdx.x;
    int row = idx >> 9;
    int pc  = idx & 511;
    int t   = row & (SEQL - 1);
    int i   = pc & 31;
    float c = ct[(t << 5) + i];
    float s = st[(t << 5) + i];
    float2* p = (float2*)(x + ((size_t)row << 10)) + pc;
    float2 v = *p;
    float2 r;
    r.x = v.x * c - v.y * s;
    r.y = v.y * c + v.x * s;
    *p = r;
}

// ---------------- C = alpha * (A @ W^T + bias) -------------------------------
// 128x128x8 block tile, 256 threads, 8x8 per-thread fragments.
__global__ __launch_bounds__(256) void gemm_nt_bias_kernel(
    const float* __restrict__ A, const float* __restrict__ W,
    const float* __restrict__ bias, float* __restrict__ C,
    int M, int N, int K, float alpha)
{
    __shared__ float As[8][132];  // [k][m], stride 132 -> conflict-free transposed STS
    __shared__ float Ws[8][132];  // [k][n]

    const int tid = threadIdx.x;
    const int tx = tid & 15;
    const int ty = tid >> 4;
    const int m0 = blockIdx.y << 7;
    const int n0 = blockIdx.x << 7;

    const int lrow = tid >> 1;          // 0..127
    const int lk   = (tid & 1) << 2;    // 0 or 4

    const float* Ap = A + (size_t)(m0 + lrow) * K + lk;
    const float* Wp = W + (size_t)(n0 + lrow) * K + lk;

    float4 aR = *(const float4*)Ap;
    float4 wR = *(const float4*)Wp;

    float acc[8][8] = {};

    for (int k0 = 0; k0 < K; k0 += 8) {
        As[lk + 0][lrow] = aR.x; As[lk + 1][lrow] = aR.y;
        As[lk + 2][lrow] = aR.z; As[lk + 3][lrow] = aR.w;
        Ws[lk + 0][lrow] = wR.x; Ws[lk + 1][lrow] = wR.y;
        Ws[lk + 2][lrow] = wR.z; Ws[lk + 3][lrow] = wR.w;
        __syncthreads();

        if (k0 + 8 < K) {
            aR = *(const float4*)(Ap + k0 + 8);
            wR = *(const float4*)(Wp + k0 + 8);
        }

#pragma unroll
        for (int kk = 0; kk < 8; kk++) {
            float4 a0 = *(const float4*)&As[kk][ty << 3];
            float4 a1 = *(const float4*)&As[kk][(ty << 3) + 4];
            float4 b0 = *(const float4*)&Ws[kk][tx << 3];
            float4 b1 = *(const float4*)&Ws[kk][(tx << 3) + 4];
            float a[8] = {a0.x, a0.y, a0.z, a0.w, a1.x, a1.y, a1.z, a1.w};
            float b[8] = {b0.x, b0.y, b0.z, b0.w, b1.x, b1.y, b1.z, b1.w};
#pragma unroll
            for (int i = 0; i < 8; i++)
#pragma unroll
                for (int j = 0; j < 8; j++)
                    acc[i][j] = fmaf(a[i], b[j], acc[i][j]);
        }
        __syncthreads();
    }

    const int cb = n0 + (tx << 3);
    float4 bv0 = *(const float4*)(bias + cb);
    float4 bv1 = *(const float4*)(bias + cb + 4);
#pragma unroll
    for (int i = 0; i < 8; i++) {
        int r = m0 + (ty << 3) + i;
        float4 w0, w1;
        w0.x = alpha * (acc[i][0] + bv0.x);
        w0.y = alpha * (acc[i][1] + bv0.y);
        w0.z = alpha * (acc[i][2] + bv0.z);
        w0.w = alpha * (acc[i][3] + bv0.w);
        w1.x = alpha * (acc[i][4] + bv1.x);
        w1.y = alpha * (acc[i][5] + bv1.y);
        w1.z = alpha * (acc[i][6] + bv1.z);
        w1.w = alpha * (acc[i][7] + bv1.w);
        *(float4*)(C + (size_t)r * N + cb)     = w0;
        *(float4*)(C + (size_t)r * N + cb + 4) = w1;
    }
}

// ---------------- flash attention, per (b,h, 64-query tile) ------------------
// 128 threads: tx 0..15 (4 k-cols / 4 d-cols each), ty 0..7 (8 q-rows each).
// Qst / KP(K^T phase) use an XOR float4 swizzle on the column index:
//   element (d, c) stored at row d, phys col ((c>>2) ^ (d>>2))*4 + (c&3).
__global__ __launch_bounds__(128) void attn_kernel(
    const float* __restrict__ Q, const float* __restrict__ K,
    const float* __restrict__ V, float* __restrict__ O)
{
    __shared__ float Qst[64][64];  // Q^T, swizzled
    __shared__ float KP[64][64];   // K^T swizzled, then P [r][c] linear
    __shared__ float Vs[64][64];   // [c][d] linear

    const int tid = threadIdx.x;
    const int tx = tid & 15;
    const int ty = tid >> 4;

    const int bh = blockIdx.x;
    const int qt = blockIdx.y;
    const int b  = bh >> 4;
    const int h  = bh & 15;

    const float* qb = Q + ((size_t)(b * SEQL) + qt * 64) * EMB + h * HD;
    const float* kb = K + (size_t)(b * SEQL) * EMB + h * HD;
    const float* vb = V + (size_t)(b * SEQL) * EMB + h * HD;
    float*       ob = O + ((size_t)(b * SEQL) + qt * 64) * EMB + h * HD;

    // load Q tile transposed + swizzled
#pragma unroll
    for (int it = 0; it < 8; it++) {
        int f  = tid + (it << 7);
        int r  = f >> 4;
        int d4 = (f & 15) << 2;
        float4 v = *(const float4*)(qb + (size_t)r * EMB + d4);
        int cs = (((r >> 2) ^ (d4 >> 2)) << 2) | (r & 3);
        Qst[d4 + 0][cs] = v.x; Qst[d4 + 1][cs] = v.y;
        Qst[d4 + 2][cs] = v.z; Qst[d4 + 3][cs] = v.w;
    }

    float o[8][4] = {};
    float m_run[8], l_run[8];
#pragma unroll
    for (int i = 0; i < 8; i++) { m_run[i] = -INFINITY; l_run[i] = 0.0f; }

    for (int kt = 0; kt < SEQL / 64; kt++) {
        __syncthreads();  // prior PV reads of KP/Vs done
#pragma unroll
        for (int it = 0; it < 8; it++) {
            int f  = tid + (it << 7);
            int r  = f >> 4;
            int d4 = (f & 15) << 2;
            float4 kv = *(const float4*)(kb + (size_t)(kt * 64 + r) * EMB + d4);
            int cs = (((r >> 2) ^ (d4 >> 2)) << 2) | (r & 3);
            KP[d4 + 0][cs] = kv.x; KP[d4 + 1][cs] = kv.y;
            KP[d4 + 2][cs] = kv.z; KP[d4 + 3][cs] = kv.w;
            float4 vv = *(const float4*)(vb + (size_t)(kt * 64 + r) * EMB + d4);
            *(float4*)&Vs[r][d4] = vv;
        }
        __syncthreads();

        // S = Q @ K^T : s[i][j], q = ty*8+i, k = tx*4+j
        float s[8][4] = {};
#pragma unroll
        for (int dd = 0; dd < 64; dd++) {
            int sw = dd >> 2;
            float4 a0 = *(const float4*)&Qst[dd][(((ty << 1)    ) ^ sw) << 2];
            float4 a1 = *(const float4*)&Qst[dd][(((ty << 1) | 1) ^ sw) << 2];
            float4 bf = *(const float4*)&KP[dd][(tx ^ sw) << 2];
            float a[8] = {a0.x, a0.y, a0.z, a0.w, a1.x, a1.y, a1.z, a1.w};
            float bb[4] = {bf.x, bf.y, bf.z, bf.w};
#pragma unroll
            for (int i = 0; i < 8; i++)
#pragma unroll
                for (int j = 0; j < 4; j++)
                    s[i][j] = fmaf(a[i], bb[j], s[i][j]);
        }

        // online softmax (16 threads per q-row: fixed ty, all tx)
#pragma unroll
        for (int i = 0; i < 8; i++) {
            float tm = fmaxf(fmaxf(s[i][0], s[i][1]), fmaxf(s[i][2], s[i][3]));
#pragma unroll
            for (int msk = 1; msk < 16; msk <<= 1)
                tm = fmaxf(tm, __shfl_xor_sync(0xffffffffu, tm, msk));
            float nm = fmaxf(m_run[i], tm);
            float al = __expf(m_run[i] - nm);
            float ts = 0.0f;
#pragma unroll
            for (int j = 0; j < 4; j++) {
                s[i][j] = __expf(s[i][j] - nm);
                ts += s[i][j];
            }
#pragma unroll
            for (int msk = 1; msk < 16; msk <<= 1)
                ts += __shfl_xor_sync(0xffffffffu, ts, msk);
            l_run[i] = l_run[i] * al + ts;
            m_run[i] = nm;
#pragma unroll
            for (int j = 0; j < 4; j++) o[i][j] *= al;
        }

        __syncthreads();  // done reading K^T from KP
        // store P linear: KP[q][c]
#pragma unroll
        for (int i = 0; i < 8; i++) {
            float4 pv = {s[i][0], s[i][1], s[i][2], s[i][3]};
            *(float4*)&KP[(ty << 3) + i][tx << 2] = pv;
        }
        __syncthreads();

        // O += P @ V : per 4-key chunk
#pragma unroll
        for (int c4 = 0; c4 < 16; c4++) {
            float4 v0 = *(const float4*)&Vs[(c4 << 2) + 0][tx << 2];
            float4 v1 = *(const float4*)&Vs[(c4 << 2) + 1][tx << 2];
            float4 v2 = *(const float4*)&Vs[(c4 << 2) + 2][tx << 2];
            float4 v3 = *(const float4*)&Vs[(c4 << 2) + 3][tx << 2];
#pragma unroll
            for (int i = 0; i < 8; i++) {
                float4 pq = *(const float4*)&KP[(ty << 3) + i][c4 << 2];
                o[i][0] = fmaf(pq.x, v0.x, o[i][0]);
                o[i][1] = fmaf(pq.x, v0.y, o[i][1]);
                o[i][2] = fmaf(pq.x, v0.z, o[i][2]);
                o[i][3] = fmaf(pq.x, v0.w, o[i][3]);
                o[i][0] = fmaf(pq.y, v1.x, o[i][0]);
                o[i][1] = fmaf(pq.y, v1.y, o[i][1]);
                o[i][2] = fmaf(pq.y, v1.z, o[i][2]);
                o[i][3] = fmaf(pq.y, v1.w, o[i][3]);
                o[i][0] = fmaf(pq.z, v2.x, o[i][0]);
                o[i][1] = fmaf(pq.z, v2.y, o[i][1]);
                o[i][2] = fmaf(pq.z, v2.z, o[i][2]);
                o[i][3] = fmaf(pq.z, v2.w, o[i][3]);
                o[i][0] = fmaf(pq.w, v3.x, o[i][0]);
                o[i][1] = fmaf(pq.w, v3.y, o[i][1]);
                o[i][2] = fmaf(pq.w, v3.z, o[i][2]);
                o[i][3] = fmaf(pq.w, v3.w, o[i][3]);
            }
        }
    }

#pragma unroll
    for (int i = 0; i < 8; i++) {
        float inv = 1.0f / l_run[i];
        float4 w;
        w.x = o[i][0] * inv; w.y = o[i][1] * inv;
        w.z = o[i][2] * inv; w.w = o[i][3] * inv;
        *(float4*)(ob + (size_t)((ty << 3) + i) * EMB + (tx << 2)) = w;
    }
}

// ---------------- launch ------------------------------------------------------
extern "C" void kernel_launch(void* const* d_in, const int* in_sizes, int n_in,
                              void* d_out, int out_size) {
    const float* query = (const float*)d_in[0];
    const float* key_  = (const float*)d_in[1];
    const float* value = (const float*)d_in[2];
    const float* wq = (const float*)d_in[3];
    const float* bq = (const float*)d_in[4];
    const float* wk = (const float*)d_in[5];
    const float* bk = (const float*)d_in[6];
    const float* wv = (const float*)d_in[7];
    const float* bv = (const float*)d_in[8];
    const float* wo = (const float*)d_in[9];
    const float* bo = (const float*)d_in[10];
    float* out = (float*)d_out;

    float *qp, *kp, *vp, *ap, *cq, *sq, *ck, *sk;
    cudaGetSymbolAddress((void**)&qp, g_q);
    cudaGetSymbolAddress((void**)&kp, g_k);
    cudaGetSymbolAddress((void**)&vp, g_v);
    cudaGetSymbolAddress((void**)&ap, g_attn);
    cudaGetSymbolAddress((void**)&cq, g_cq);
    cudaGetSymbolAddress((void**)&sq, g_sq);
    cudaGetSymbolAddress((void**)&ck, g_ck);
    cudaGetSymbolAddress((void**)&sk, g_sk);

    build_tables_kernel<<<(SEQL * 32 + 255) / 256, 256>>>();

    dim3 gg(EMB / 128, MTOT / 128);  // (8, 64)
    const float scaling = 0.125f;    // HD^-0.5
    gemm_nt_bias_kernel<<<gg, 256>>>(query, wq, bq, qp, MTOT, EMB, EMB, scaling);
    gemm_nt_bias_kernel<<<gg, 256>>>(key_,  wk, bk, kp, MTOT, EMB, EMB, 1.0f);
    gemm_nt_bias_kernel<<<gg, 256>>>(value, wv, bv, vp, MTOT, EMB, EMB, 1.0f);

    int npair = MTOT * (EMB / 2);
    xpos_apply_kernel<<<npair / 256, 256>>>(qp, cq, sq);
    xpos_apply_kernel<<<npair / 256, 256>>>(kp, ck, sk);

    attn_kernel<<<dim3(BSZ * NH, SEQL / 64), 128>>>(qp, kp, vp, ap);

    gemm_nt_bias_kernel<<<gg, 256>>>(ap, wo, bo, out, MTOT, EMB, EMB, 1.0f);
}

// round 4
// speedup vs baseline: 2.0918x; 1.5722x over previous
#include <cuda_runtime.h>
#include <cstdint>
#include <math.h>

#define BSZ  8
#define SEQL 1024
#define EMB  1024
#define NH   16
#define HD   64
#define MTOT (BSZ * SEQL)   // 8192

// ---------------- scratch (device globals; no allocations allowed) ----------
__device__ float g_q[MTOT * EMB];
__device__ float g_k[MTOT * EMB];
__device__ float g_v[MTOT * EMB];
__device__ float g_attn[MTOT * EMB];
__device__ float g_cq[SEQL * 32];
__device__ float g_sq[SEQL * 32];
__device__ float g_ck[SEQL * 32];
__device__ float g_sk[SEQL * 32];

// ---------------- xpos cos/sin * scale tables --------------------------------
__global__ void build_tables_kernel() {
    int idx = blockIdx.x * blockDim.x + threadIdx.x;
    if (idx >= SEQL * 32) return;
    int t = idx >> 5;
    int i = idx & 31;
    float s_i   = (2.0f * (float)i + 0.4f * (float)HD) / (1.4f * (float)HD);
    float pos   = (float)t - (float)(SEQL / 2);
    float scale = powf(s_i, pos / (float)EMB);
    float invf  = powf(10000.0f, -(float)i / (float)(HD / 2));
    float sn, cs;
    sincosf((float)t * invf, &sn, &cs);
    g_cq[idx] = cs * scale;
    g_sq[idx] = sn * scale;
    g_ck[idx] = cs / scale;
    g_sk[idx] = sn / scale;
}

// ---------------- xpos rotation (in place) -----------------------------------
__global__ void xpos_apply_kernel(float* __restrict__ x,
                                  const float* __restrict__ ct,
                                  const float* __restrict__ st) {
    int idx = blockIdx.x * blockDim.x + threadIdx.x;
    int row = idx >> 9;
    int pc  = idx & 511;
    int t   = row & (SEQL - 1);
    int i   = pc & 31;
    float c = ct[(t << 5) + i];
    float s = st[(t << 5) + i];
    float2* p = (float2*)(x + ((size_t)row << 10)) + pc;
    float2 v = *p;
    float2 r;
    r.x = v.x * c - v.y * s;
    r.y = v.y * c + v.x * s;
    *p = r;
}

// ---------------- tf32 helpers ------------------------------------------------
static __device__ __forceinline__ uint32_t f2tf32(float f) {
    uint32_t u;
    asm("cvt.rna.tf32.f32 %0, %1;" : "=r"(u) : "f"(f));
    return u;
}

#define MMA_TF32(c, a, b) \
    asm volatile("mma.sync.aligned.m16n8k8.row.col.f32.tf32.tf32.f32 " \
        "{%0,%1,%2,%3}, {%4,%5,%6,%7}, {%8,%9}, {%0,%1,%2,%3};" \
        : "+f"((c)[0]), "+f"((c)[1]), "+f"((c)[2]), "+f"((c)[3]) \
        : "r"((a)[0]), "r"((a)[1]), "r"((a)[2]), "r"((a)[3]), \
          "r"((b)[0]), "r"((b)[1]))

// ---------------- C = alpha * (A @ W^T + bias) via mma.sync tf32 -------------
// CTA 128x128, 8 warps (2x4), warp tile 64x32, K-chunk 16, double buffered.
// smem [row][k] stride 20 -> conflict-free m16n8k8 fragment loads.
#define KC 16
#define KPAD 20

__global__ __launch_bounds__(256, 2) void gemm_mma_kernel(
    const float* __restrict__ A, const float* __restrict__ W,
    const float* __restrict__ bias, float* __restrict__ C, float alpha)
{
    __shared__ __align__(16) uint32_t As[2][128][KPAD];
    __shared__ __align__(16) uint32_t Ws[2][128][KPAD];

    const int tid  = threadIdx.x;
    const int lane = tid & 31;
    const int wid  = tid >> 5;
    const int m0 = blockIdx.y << 7;
    const int n0 = blockIdx.x << 7;
    const int wm = (wid >> 2) << 6;   // 0 / 64
    const int wn = (wid & 3) << 5;    // 0,32,64,96

    // fill mapping: 2 threads per row, each covers 8 k-values
    const int fm = tid >> 1;
    const int fk = (tid & 1) << 3;
    const float* Ap = A + (size_t)(m0 + fm) * EMB + fk;
    const float* Wp = W + (size_t)(n0 + fm) * EMB + fk;

    uint32_t ra[8], rw[8];
    auto fetch = [&](int k0) {
        float4 a0 = *(const float4*)(Ap + k0);
        float4 a1 = *(const float4*)(Ap + k0 + 4);
        float4 w0 = *(const float4*)(Wp + k0);
        float4 w1 = *(const float4*)(Wp + k0 + 4);
        ra[0] = f2tf32(a0.x); ra[1] = f2tf32(a0.y); ra[2] = f2tf32(a0.z); ra[3] = f2tf32(a0.w);
        ra[4] = f2tf32(a1.x); ra[5] = f2tf32(a1.y); ra[6] = f2tf32(a1.z); ra[7] = f2tf32(a1.w);
        rw[0] = f2tf32(w0.x); rw[1] = f2tf32(w0.y); rw[2] = f2tf32(w0.z); rw[3] = f2tf32(w0.w);
        rw[4] = f2tf32(w1.x); rw[5] = f2tf32(w1.y); rw[6] = f2tf32(w1.z); rw[7] = f2tf32(w1.w);
    };
    auto stbuf = [&](int b) {
        *(uint4*)&As[b][fm][fk]     = make_uint4(ra[0], ra[1], ra[2], ra[3]);
        *(uint4*)&As[b][fm][fk + 4] = make_uint4(ra[4], ra[5], ra[6], ra[7]);
        *(uint4*)&Ws[b][fm][fk]     = make_uint4(rw[0], rw[1], rw[2], rw[3]);
        *(uint4*)&Ws[b][fm][fk + 4] = make_uint4(rw[4], rw[5], rw[6], rw[7]);
    };

    fetch(0);
    stbuf(0);
    __syncthreads();

    float c[4][4][4];
#pragma unroll
    for (int mf = 0; mf < 4; mf++)
#pragma unroll
        for (int nf = 0; nf < 4; nf++)
#pragma unroll
            for (int q = 0; q < 4; q++) c[mf][nf][q] = 0.0f;

    const int NK = EMB / KC;  // 64
    const int qrow = lane >> 2;
    const int qcol = lane & 3;

    for (int kt = 0; kt < NK; kt++) {
        const int b = kt & 1;
        if (kt + 1 < NK) fetch((kt + 1) * KC);

#pragma unroll
        for (int k8 = 0; k8 < KC; k8 += 8) {
            uint32_t af[4][4], bf[4][2];
#pragma unroll
            for (int mf = 0; mf < 4; mf++) {
                int r = wm + (mf << 4) + qrow;
                af[mf][0] = As[b][r][k8 + qcol];
                af[mf][1] = As[b][r + 8][k8 + qcol];
                af[mf][2] = As[b][r][k8 + qcol + 4];
                af[mf][3] = As[b][r + 8][k8 + qcol + 4];
            }
#pragma unroll
            for (int nf = 0; nf < 4; nf++) {
                int n = wn + (nf << 3) + qrow;
                bf[nf][0] = Ws[b][n][k8 + qcol];
                bf[nf][1] = Ws[b][n][k8 + qcol + 4];
            }
#pragma unroll
            for (int mf = 0; mf < 4; mf++)
#pragma unroll
                for (int nf = 0; nf < 4; nf++)
                    MMA_TF32(c[mf][nf], af[mf], bf[nf]);
        }
        __syncthreads();
        if (kt + 1 < NK) {
            stbuf(b ^ 1);
            __syncthreads();
        }
    }

    // epilogue: alpha * (acc + bias)
#pragma unroll
    for (int mf = 0; mf < 4; mf++) {
        int r0 = m0 + wm + (mf << 4) + qrow;
#pragma unroll
        for (int nf = 0; nf < 4; nf++) {
            int cb = n0 + wn + (nf << 3) + (qcol << 1);
            float2 bv = *(const float2*)(bias + cb);
            float2 o0, o1;
            o0.x = alpha * (c[mf][nf][0] + bv.x);
            o0.y = alpha * (c[mf][nf][1] + bv.y);
            o1.x = alpha * (c[mf][nf][2] + bv.x);
            o1.y = alpha * (c[mf][nf][3] + bv.y);
            *(float2*)(C + (size_t)r0 * EMB + cb)       = o0;
            *(float2*)(C + (size_t)(r0 + 8) * EMB + cb) = o1;
        }
    }
}

// ---------------- flash attention, per (b,h, 64-query tile) ------------------
__global__ __launch_bounds__(128) void attn_kernel(
    const float* __restrict__ Q, const float* __restrict__ K,
    const float* __restrict__ V, float* __restrict__ O)
{
    __shared__ float Qst[64][64];
    __shared__ float KP[64][64];
    __shared__ float Vs[64][64];

    const int tid = threadIdx.x;
    const int tx = tid & 15;
    const int ty = tid >> 4;

    const int bh = blockIdx.x;
    const int qt = blockIdx.y;
    const int b  = bh >> 4;
    const int h  = bh & 15;

    const float* qb = Q + ((size_t)(b * SEQL) + qt * 64) * EMB + h * HD;
    const float* kb = K + (size_t)(b * SEQL) * EMB + h * HD;
    const float* vb = V + (size_t)(b * SEQL) * EMB + h * HD;
    float*       ob = O + ((size_t)(b * SEQL) + qt * 64) * EMB + h * HD;

#pragma unroll
    for (int it = 0; it < 8; it++) {
        int f  = tid + (it << 7);
        int r  = f >> 4;
        int d4 = (f & 15) << 2;
        float4 v = *(const float4*)(qb + (size_t)r * EMB + d4);
        int cs = (((r >> 2) ^ (d4 >> 2)) << 2) | (r & 3);
        Qst[d4 + 0][cs] = v.x; Qst[d4 + 1][cs] = v.y;
        Qst[d4 + 2][cs] = v.z; Qst[d4 + 3][cs] = v.w;
    }

    float o[8][4] = {};
    float m_run[8], l_run[8];
#pragma unroll
    for (int i = 0; i < 8; i++) { m_run[i] = -INFINITY; l_run[i] = 0.0f; }

    for (int kt = 0; kt < SEQL / 64; kt++) {
        __syncthreads();
#pragma unroll
        for (int it = 0; it < 8; it++) {
            int f  = tid + (it << 7);
            int r  = f >> 4;
            int d4 = (f & 15) << 2;
            float4 kv = *(const float4*)(kb + (size_t)(kt * 64 + r) * EMB + d4);
            int cs = (((r >> 2) ^ (d4 >> 2)) << 2) | (r & 3);
            KP[d4 + 0][cs] = kv.x; KP[d4 + 1][cs] = kv.y;
            KP[d4 + 2][cs] = kv.z; KP[d4 + 3][cs] = kv.w;
            float4 vv = *(const float4*)(vb + (size_t)(kt * 64 + r) * EMB + d4);
            *(float4*)&Vs[r][d4] = vv;
        }
        __syncthreads();

        float s[8][4] = {};
#pragma unroll
        for (int dd = 0; dd < 64; dd++) {
            int sw = dd >> 2;
            float4 a0 = *(const float4*)&Qst[dd][(((ty << 1)    ) ^ sw) << 2];
            float4 a1 = *(const float4*)&Qst[dd][(((ty << 1) | 1) ^ sw) << 2];
            float4 bf = *(const float4*)&KP[dd][(tx ^ sw) << 2];
            float a[8] = {a0.x, a0.y, a0.z, a0.w, a1.x, a1.y, a1.z, a1.w};
            float bb[4] = {bf.x, bf.y, bf.z, bf.w};
#pragma unroll
            for (int i = 0; i < 8; i++)
#pragma unroll
                for (int j = 0; j < 4; j++)
                    s[i][j] = fmaf(a[i], bb[j], s[i][j]);
        }

#pragma unroll
        for (int i = 0; i < 8; i++) {
            float tm = fmaxf(fmaxf(s[i][0], s[i][1]), fmaxf(s[i][2], s[i][3]));
#pragma unroll
            for (int msk = 1; msk < 16; msk <<= 1)
                tm = fmaxf(tm, __shfl_xor_sync(0xffffffffu, tm, msk));
            float nm = fmaxf(m_run[i], tm);
            float al = __expf(m_run[i] - nm);
            float ts = 0.0f;
#pragma unroll
            for (int j = 0; j < 4; j++) {
                s[i][j] = __expf(s[i][j] - nm);
                ts += s[i][j];
            }
#pragma unroll
            for (int msk = 1; msk < 16; msk <<= 1)
                ts += __shfl_xor_sync(0xffffffffu, ts, msk);
            l_run[i] = l_run[i] * al + ts;
            m_run[i] = nm;
#pragma unroll
            for (int j = 0; j < 4; j++) o[i][j] *= al;
        }

        __syncthreads();
#pragma unroll
        for (int i = 0; i < 8; i++) {
            float4 pv = {s[i][0], s[i][1], s[i][2], s[i][3]};
            *(float4*)&KP[(ty << 3) + i][tx << 2] = pv;
        }
        __syncthreads();

#pragma unroll
        for (int c4 = 0; c4 < 16; c4++) {
            float4 v0 = *(const float4*)&Vs[(c4 << 2) + 0][tx << 2];
            float4 v1 = *(const float4*)&Vs[(c4 << 2) + 1][tx << 2];
            float4 v2 = *(const float4*)&Vs[(c4 << 2) + 2][tx << 2];
            float4 v3 = *(const float4*)&Vs[(c4 << 2) + 3][tx << 2];
#pragma unroll
            for (int i = 0; i < 8; i++) {
                float4 pq = *(const float4*)&KP[(ty << 3) + i][c4 << 2];
                o[i][0] = fmaf(pq.x, v0.x, o[i][0]);
                o[i][1] = fmaf(pq.x, v0.y, o[i][1]);
                o[i][2] = fmaf(pq.x, v0.z, o[i][2]);
                o[i][3] = fmaf(pq.x, v0.w, o[i][3]);
                o[i][0] = fmaf(pq.y, v1.x, o[i][0]);
                o[i][1] = fmaf(pq.y, v1.y, o[i][1]);
                o[i][2] = fmaf(pq.y, v1.z, o[i][2]);
                o[i][3] = fmaf(pq.y, v1.w, o[i][3]);
                o[i][0] = fmaf(pq.z, v2.x, o[i][0]);
                o[i][1] = fmaf(pq.z, v2.y, o[i][1]);
                o[i][2] = fmaf(pq.z, v2.z, o[i][2]);
                o[i][3] = fmaf(pq.z, v2.w, o[i][3]);
                o[i][0] = fmaf(pq.w, v3.x, o[i][0]);
                o[i][1] = fmaf(pq.w, v3.y, o[i][1]);
                o[i][2] = fmaf(pq.w, v3.z, o[i][2]);
                o[i][3] = fmaf(pq.w, v3.w, o[i][3]);
            }
        }
    }

#pragma unroll
    for (int i = 0; i < 8; i++) {
        float inv = 1.0f / l_run[i];
        float4 w;
        w.x = o[i][0] * inv; w.y = o[i][1] * inv;
        w.z = o[i][2] * inv; w.w = o[i][3] * inv;
        *(float4*)(ob + (size_t)((ty << 3) + i) * EMB + (tx << 2)) = w;
    }
}

// ---------------- launch ------------------------------------------------------
extern "C" void kernel_launch(void* const* d_in, const int* in_sizes, int n_in,
                              void* d_out, int out_size) {
    const float* query = (const float*)d_in[0];
    const float* key_  = (const float*)d_in[1];
    const float* value = (const float*)d_in[2];
    const float* wq = (const float*)d_in[3];
    const float* bq = (const float*)d_in[4];
    const float* wk = (const float*)d_in[5];
    const float* bk = (const float*)d_in[6];
    const float* wv = (const float*)d_in[7];
    const float* bv = (const float*)d_in[8];
    const float* wo = (const float*)d_in[9];
    const float* bo = (const float*)d_in[10];
    float* out = (float*)d_out;

    float *qp, *kp, *vp, *ap, *cq, *sq, *ck, *sk;
    cudaGetSymbolAddress((void**)&qp, g_q);
    cudaGetSymbolAddress((void**)&kp, g_k);
    cudaGetSymbolAddress((void**)&vp, g_v);
    cudaGetSymbolAddress((void**)&ap, g_attn);
    cudaGetSymbolAddress((void**)&cq, g_cq);
    cudaGetSymbolAddress((void**)&sq, g_sq);
    cudaGetSymbolAddress((void**)&ck, g_ck);
    cudaGetSymbolAddress((void**)&sk, g_sk);

    build_tables_kernel<<<(SEQL * 32 + 255) / 256, 256>>>();

    dim3 gg(EMB / 128, MTOT / 128);  // (8, 64)
    const float scaling = 0.125f;    // HD^-0.5
    gemm_mma_kernel<<<gg, 256>>>(query, wq, bq, qp, scaling);
    gemm_mma_kernel<<<gg, 256>>>(key_,  wk, bk, kp, 1.0f);
    gemm_mma_kernel<<<gg, 256>>>(value, wv, bv, vp, 1.0f);

    int npair = MTOT * (EMB / 2);
    xpos_apply_kernel<<<npair / 256, 256>>>(qp, cq, sq);
    xpos_apply_kernel<<<npair / 256, 256>>>(kp, ck, sk);

    attn_kernel<<<dim3(BSZ * NH, SEQL / 64), 128>>>(qp, kp, vp, ap);

    gemm_mma_kernel<<<gg, 256>>>(ap, wo, bo, out, 1.0f);
}

// round 5
// speedup vs baseline: 2.5324x; 1.2106x over previous
#include <cuda_runtime.h>
#include <cstdint>
#include <math.h>

#define BSZ  8
#define SEQL 1024
#define EMB  1024
#define NH   16
#define HD   64
#define MTOT (BSZ * SEQL)   // 8192

// ---------------- scratch (device globals; no allocations allowed) ----------
__device__ float g_q[MTOT * EMB];
__device__ float g_k[MTOT * EMB];
__device__ float g_v[MTOT * EMB];
__device__ float g_vt[BSZ * NH * HD * SEQL];   // V^T per (b,h): [bh][d][t]
__device__ float g_attn[MTOT * EMB];
__device__ float g_cq[SEQL * 32];
__device__ float g_sq[SEQL * 32];
__device__ float g_ck[SEQL * 32];
__device__ float g_sk[SEQL * 32];

// ---------------- xpos cos/sin * scale tables --------------------------------
__global__ void build_tables_kernel() {
    int idx = blockIdx.x * blockDim.x + threadIdx.x;
    if (idx >= SEQL * 32) return;
    int t = idx >> 5;
    int i = idx & 31;
    float s_i   = (2.0f * (float)i + 0.4f * (float)HD) / (1.4f * (float)HD);
    float pos   = (float)t - (float)(SEQL / 2);
    float scale = powf(s_i, pos / (float)EMB);
    float invf  = powf(10000.0f, -(float)i / (float)(HD / 2));
    float sn, cs;
    sincosf((float)t * invf, &sn, &cs);
    g_cq[idx] = cs * scale;
    g_sq[idx] = sn * scale;
    g_ck[idx] = cs / scale;
    g_sk[idx] = sn / scale;
}

// ---------------- tf32 helpers ------------------------------------------------
static __device__ __forceinline__ uint32_t f2tf32(float f) {
    uint32_t u;
    asm("cvt.rna.tf32.f32 %0, %1;" : "=r"(u) : "f"(f));
    return u;
}

#define MMA_TF32(c, a, b) \
    asm volatile("mma.sync.aligned.m16n8k8.row.col.f32.tf32.tf32.f32 " \
        "{%0,%1,%2,%3}, {%4,%5,%6,%7}, {%8,%9}, {%0,%1,%2,%3};" \
        : "+f"((c)[0]), "+f"((c)[1]), "+f"((c)[2]), "+f"((c)[3]) \
        : "r"((a)[0]), "r"((a)[1]), "r"((a)[2]), "r"((a)[3]), \
          "r"((b)[0]), "r"((b)[1]))

// permuted k index: fragment pairs (k, k+4) become adjacent -> LDS.64
static __device__ __forceinline__ int kperm(int k) {
    return (k & ~7) | ((k & 3) << 1) | ((k >> 2) & 1);
}

// ---------------- C = alpha * (A @ W^T + bias) via mma.sync tf32 -------------
#define KC 16
#define KPAD 20

__global__ __launch_bounds__(256, 2) void gemm_mma_kernel(
    const float* __restrict__ A, const float* __restrict__ W,
    const float* __restrict__ bias, float* __restrict__ C, float alpha)
{
    __shared__ __align__(16) uint32_t As[2][128][KPAD];
    __shared__ __align__(16) uint32_t Ws[2][128][KPAD];

    const int tid  = threadIdx.x;
    const int lane = tid & 31;
    const int wid  = tid >> 5;
    const int m0 = blockIdx.y << 7;
    const int n0 = blockIdx.x << 7;
    const int wm = (wid >> 2) << 6;
    const int wn = (wid & 3) << 5;

    const int fm = tid >> 1;
    const int fk = (tid & 1) << 3;
    const float* Ap = A + (size_t)(m0 + fm) * EMB + fk;
    const float* Wp = W + (size_t)(n0 + fm) * EMB + fk;

    uint32_t ra[8], rw[8];
    auto fetch = [&](int k0) {
        float4 a0 = *(const float4*)(Ap + k0);
        float4 a1 = *(const float4*)(Ap + k0 + 4);
        float4 w0 = *(const float4*)(Wp + k0);
        float4 w1 = *(const float4*)(Wp + k0 + 4);
        ra[0] = f2tf32(a0.x); ra[1] = f2tf32(a0.y); ra[2] = f2tf32(a0.z); ra[3] = f2tf32(a0.w);
        ra[4] = f2tf32(a1.x); ra[5] = f2tf32(a1.y); ra[6] = f2tf32(a1.z); ra[7] = f2tf32(a1.w);
        rw[0] = f2tf32(w0.x); rw[1] = f2tf32(w0.y); rw[2] = f2tf32(w0.z); rw[3] = f2tf32(w0.w);
        rw[4] = f2tf32(w1.x); rw[5] = f2tf32(w1.y); rw[6] = f2tf32(w1.z); rw[7] = f2tf32(w1.w);
    };
    // permuted store: (k, k+4) pair -> adjacent cols
    auto stbuf = [&](int b) {
#pragma unroll
        for (int j = 0; j < 4; j++) {
            *(uint2*)&As[b][fm][fk + 2 * j] = make_uint2(ra[j], ra[j + 4]);
            *(uint2*)&Ws[b][fm][fk + 2 * j] = make_uint2(rw[j], rw[j + 4]);
        }
    };

    fetch(0);
    stbuf(0);

    float c[4][4][4];
#pragma unroll
    for (int mf = 0; mf < 4; mf++)
#pragma unroll
        for (int nf = 0; nf < 4; nf++)
#pragma unroll
            for (int q = 0; q < 4; q++) c[mf][nf][q] = 0.0f;

    const int NK = EMB / KC;
    const int qrow = lane >> 2;
    const int qcol = lane & 3;

    for (int kt = 0; kt < NK; kt++) {
        const int b = kt & 1;
        __syncthreads();
        if (kt + 1 < NK) fetch((kt + 1) * KC);

#pragma unroll
        for (int k8 = 0; k8 < KC; k8 += 8) {
            uint32_t af[4][4], bf[4][2];
#pragma unroll
            for (int mf = 0; mf < 4; mf++) {
                int r = wm + (mf << 4) + qrow;
                uint2 q0 = *(uint2*)&As[b][r][k8 + 2 * qcol];
                uint2 q1 = *(uint2*)&As[b][r + 8][k8 + 2 * qcol];
                af[mf][0] = q0.x; af[mf][1] = q1.x;
                af[mf][2] = q0.y; af[mf][3] = q1.y;
            }
#pragma unroll
            for (int nf = 0; nf < 4; nf++) {
                int n = wn + (nf << 3) + qrow;
                uint2 q = *(uint2*)&Ws[b][n][k8 + 2 * qcol];
                bf[nf][0] = q.x; bf[nf][1] = q.y;
            }
#pragma unroll
            for (int mf = 0; mf < 4; mf++)
#pragma unroll
                for (int nf = 0; nf < 4; nf++)
                    MMA_TF32(c[mf][nf], af[mf], bf[nf]);
        }
        if (kt + 1 < NK) stbuf(b ^ 1);
    }

#pragma unroll
    for (int mf = 0; mf < 4; mf++) {
        int r0 = m0 + wm + (mf << 4) + qrow;
#pragma unroll
        for (int nf = 0; nf < 4; nf++) {
            int cb = n0 + wn + (nf << 3) + (qcol << 1);
            float2 bv = *(const float2*)(bias + cb);
            float2 o0, o1;
            o0.x = alpha * (c[mf][nf][0] + bv.x);
            o0.y = alpha * (c[mf][nf][1] + bv.y);
            o1.x = alpha * (c[mf][nf][2] + bv.x);
            o1.y = alpha * (c[mf][nf][3] + bv.y);
            *(float2*)(C + (size_t)r0 * EMB + cb)       = o0;
            *(float2*)(C + (size_t)(r0 + 8) * EMB + cb) = o1;
        }
    }
}

// ---------------- V transpose: g_v [b*1024+t][h*64+d] -> g_vt [bh][d][t] ------
__global__ __launch_bounds__(256) void transpose_v_kernel(
    const float* __restrict__ V, float* __restrict__ VT)
{
    __shared__ float tile[32][33];
    const int t0 = blockIdx.x << 5;
    const int d0 = blockIdx.y << 5;
    const int bh = blockIdx.z;
    const int b  = bh >> 4;
    const int h  = bh & 15;
    const int txx = threadIdx.x & 31;
    const int tyy = threadIdx.x >> 5;   // 0..7
#pragma unroll
    for (int i = 0; i < 4; i++) {
        int t = t0 + tyy + (i << 3);
        tile[tyy + (i << 3)][txx] =
            V[(size_t)(b * SEQL + t) * EMB + h * HD + d0 + txx];
    }
    __syncthreads();
#pragma unroll
    for (int i = 0; i < 4; i++) {
        int d = d0 + tyy + (i << 3);
        VT[(size_t)(bh * HD + d) * SEQL + t0 + txx] = tile[txx][tyy + (i << 3)];
    }
}

// ---------------- tensor-core flash attention ---------------------------------
// CTA: (bh, 128-row q tile). 256 thr, 8 warps; warp owns 16 q rows.
// Dynamic smem: Qs[128][68], Ps[128][68], Ks[64][68], Vt[64][68] (tf32, permuted k).
#define ATT_SMEM ((128 + 128 + 64 + 64) * 68 * 4)

__global__ __launch_bounds__(256) void attn_mma_kernel(
    const float* __restrict__ Q, const float* __restrict__ K,
    const float* __restrict__ VT, float* __restrict__ O)
{
    extern __shared__ __align__(16) uint32_t dsm[];
    uint32_t (*Qs)[68] = (uint32_t(*)[68])dsm;
    uint32_t (*Ps)[68] = (uint32_t(*)[68])(dsm + 128 * 68);
    uint32_t (*Ks)[68] = (uint32_t(*)[68])(dsm + 256 * 68);
    uint32_t (*Vt)[68] = (uint32_t(*)[68])(dsm + 320 * 68);

    const int tid  = threadIdx.x;
    const int lane = tid & 31;
    const int wid  = tid >> 5;
    const int u = lane >> 2;       // frag row
    const int v = lane & 3;        // frag col
    const int W = wid << 4;        // warp q-row base

    const int bh = blockIdx.x;
    const int qt = blockIdx.y;
    const int b  = bh >> 4;
    const int h  = bh & 15;

    const float* qb = Q + ((size_t)(b * SEQL) + qt * 128) * EMB + h * HD;
    const float* kb = K + (size_t)(b * SEQL) * EMB + h * HD;
    const float* vtb = VT + (size_t)bh * HD * SEQL;
    float* ob = O + ((size_t)(b * SEQL) + qt * 128) * EMB + h * HD;

    // ---- fill Q (once), with xpos (upscale) ----
#pragma unroll
    for (int it = 0; it < 8; it++) {
        int f  = tid + (it << 8);
        int r  = f >> 4;
        int tx = f & 15;
        int t  = qt * 128 + r;
        float4 x = *(const float4*)(qb + (size_t)r * EMB + (tx << 2));
        float2 c0 = *(const float2*)(g_cq + t * 32 + (tx << 1));
        float2 s0 = *(const float2*)(g_sq + t * 32 + (tx << 1));
        float y0 = x.x * c0.x - x.y * s0.x;
        float y1 = x.y * c0.x + x.x * s0.x;
        float y2 = x.z * c0.y - x.w * s0.y;
        float y3 = x.w * c0.y + x.z * s0.y;
        int base = (tx >> 1) << 3;
        int hi   = tx & 1;
        Qs[r][base + 0 + hi] = f2tf32(y0);
        Qs[r][base + 2 + hi] = f2tf32(y1);
        Qs[r][base + 4 + hi] = f2tf32(y2);
        Qs[r][base + 6 + hi] = f2tf32(y3);
    }

    float o[8][4];
    float m0 = -INFINITY, m1 = -INFINITY, l0 = 0.0f, l1 = 0.0f;
#pragma unroll
    for (int nf = 0; nf < 8; nf++)
#pragma unroll
        for (int q = 0; q < 4; q++) o[nf][q] = 0.0f;

    for (int kt = 0; kt < SEQL / 64; kt++) {
        __syncthreads();   // prev PV done with Ps/Vt; prev S done with Ks
        // ---- fill K tile (xpos downscale) + Vt tile ----
#pragma unroll
        for (int it = 0; it < 4; it++) {
            int f  = tid + (it << 8);
            int r  = f >> 4;
            int tx = f & 15;
            int t  = kt * 64 + r;
            float4 x = *(const float4*)(kb + (size_t)t * EMB + (tx << 2));
            float2 c0 = *(const float2*)(g_ck + t * 32 + (tx << 1));
            float2 s0 = *(const float2*)(g_sk + t * 32 + (tx << 1));
            float y0 = x.x * c0.x - x.y * s0.x;
            float y1 = x.y * c0.x + x.x * s0.x;
            float y2 = x.z * c0.y - x.w * s0.y;
            float y3 = x.w * c0.y + x.z * s0.y;
            int base = (tx >> 1) << 3;
            int hi   = tx & 1;
            Ks[r][base + 0 + hi] = f2tf32(y0);
            Ks[r][base + 2 + hi] = f2tf32(y1);
            Ks[r][base + 4 + hi] = f2tf32(y2);
            Ks[r][base + 6 + hi] = f2tf32(y3);
            // V^T tile: rows d, cols kseq
            float4 vv = *(const float4*)(vtb + (size_t)r * SEQL + kt * 64 + (tx << 2));
            Vt[r][base + 0 + hi] = f2tf32(vv.x);
            Vt[r][base + 2 + hi] = f2tf32(vv.y);
            Vt[r][base + 4 + hi] = f2tf32(vv.z);
            Vt[r][base + 6 + hi] = f2tf32(vv.w);
        }
        __syncthreads();

        // ---- S = Q @ K^T ----
        float s[8][4];
#pragma unroll
        for (int nf = 0; nf < 8; nf++)
#pragma unroll
            for (int q = 0; q < 4; q++) s[nf][q] = 0.0f;
#pragma unroll
        for (int k8 = 0; k8 < 64; k8 += 8) {
            uint32_t af[4];
            uint2 a0 = *(uint2*)&Qs[W + u][k8 + 2 * v];
            uint2 a1 = *(uint2*)&Qs[W + u + 8][k8 + 2 * v];
            af[0] = a0.x; af[1] = a1.x; af[2] = a0.y; af[3] = a1.y;
#pragma unroll
            for (int nf = 0; nf < 8; nf++) {
                uint2 bq = *(uint2*)&Ks[(nf << 3) + u][k8 + 2 * v];
                uint32_t bf[2] = {bq.x, bq.y};
                MMA_TF32(s[nf], af, bf);
            }
        }

        // ---- online softmax (rows r0 = W+u, r1 = W+u+8; reduce over v lanes) --
        float mx0 = -INFINITY, mx1 = -INFINITY;
#pragma unroll
        for (int nf = 0; nf < 8; nf++) {
            mx0 = fmaxf(mx0, fmaxf(s[nf][0], s[nf][1]));
            mx1 = fmaxf(mx1, fmaxf(s[nf][2], s[nf][3]));
        }
        mx0 = fmaxf(mx0, __shfl_xor_sync(0xffffffffu, mx0, 1));
        mx0 = fmaxf(mx0, __shfl_xor_sync(0xffffffffu, mx0, 2));
        mx1 = fmaxf(mx1, __shfl_xor_sync(0xffffffffu, mx1, 1));
        mx1 = fmaxf(mx1, __shfl_xor_sync(0xffffffffu, mx1, 2));
        float nm0 = fmaxf(m0, mx0), nm1 = fmaxf(m1, mx1);
        float al0 = __expf(m0 - nm0), al1 = __expf(m1 - nm1);
        float ts0 = 0.0f, ts1 = 0.0f;
#pragma unroll
        for (int nf = 0; nf < 8; nf++) {
            s[nf][0] = __expf(s[nf][0] - nm0);
            s[nf][1] = __expf(s[nf][1] - nm0);
            s[nf][2] = __expf(s[nf][2] - nm1);
            s[nf][3] = __expf(s[nf][3] - nm1);
            ts0 += s[nf][0] + s[nf][1];
            ts1 += s[nf][2] + s[nf][3];
        }
        ts0 += __shfl_xor_sync(0xffffffffu, ts0, 1);
        ts0 += __shfl_xor_sync(0xffffffffu, ts0, 2);
        ts1 += __shfl_xor_sync(0xffffffffu, ts1, 1);
        ts1 += __shfl_xor_sync(0xffffffffu, ts1, 2);
        l0 = l0 * al0 + ts0; l1 = l1 * al1 + ts1;
        m0 = nm0; m1 = nm1;
#pragma unroll
        for (int nf = 0; nf < 8; nf++) {
            o[nf][0] *= al0; o[nf][1] *= al0;
            o[nf][2] *= al1; o[nf][3] *= al1;
        }

        // ---- write P (tf32, permuted cols) ----
#pragma unroll
        for (int nf = 0; nf < 8; nf++) {
            int col = (nf << 3) + (v << 1);
            int pp  = kperm(col);
            Ps[W + u][pp]         = f2tf32(s[nf][0]);
            Ps[W + u][pp + 2]     = f2tf32(s[nf][1]);
            Ps[W + u + 8][pp]     = f2tf32(s[nf][2]);
            Ps[W + u + 8][pp + 2] = f2tf32(s[nf][3]);
        }
        __syncthreads();

        // ---- O += P @ V  (B = V^T[d][kseq]) ----
#pragma unroll
        for (int k8 = 0; k8 < 64; k8 += 8) {
            uint32_t af[4];
            uint2 a0 = *(uint2*)&Ps[W + u][k8 + 2 * v];
            uint2 a1 = *(uint2*)&Ps[W + u + 8][k8 + 2 * v];
            af[0] = a0.x; af[1] = a1.x; af[2] = a0.y; af[3] = a1.y;
#pragma unroll
            for (int nf = 0; nf < 8; nf++) {
                uint2 bq = *(uint2*)&Vt[(nf << 3) + u][k8 + 2 * v];
                uint32_t bf[2] = {bq.x, bq.y};
                MMA_TF32(o[nf], af, bf);
            }
        }
    }

    // ---- epilogue ----
    float inv0 = 1.0f / l0, inv1 = 1.0f / l1;
#pragma unroll
    for (int nf = 0; nf < 8; nf++) {
        int cb = (nf << 3) + (v << 1);
        float2 w0 = {o[nf][0] * inv0, o[nf][1] * inv0};
        float2 w1 = {o[nf][2] * inv1, o[nf][3] * inv1};
        *(float2*)(ob + (size_t)(W + u) * EMB + cb)     = w0;
        *(float2*)(ob + (size_t)(W + u + 8) * EMB + cb) = w1;
    }
}

// ---------------- launch ------------------------------------------------------
extern "C" void kernel_launch(void* const* d_in, const int* in_sizes, int n_in,
                              void* d_out, int out_size) {
    const float* query = (const float*)d_in[0];
    const float* key_  = (const float*)d_in[1];
    const float* value = (const float*)d_in[2];
    const float* wq = (const float*)d_in[3];
    const float* bq = (const float*)d_in[4];
    const float* wk = (const float*)d_in[5];
    const float* bk = (const float*)d_in[6];
    const float* wv = (const float*)d_in[7];
    const float* bv = (const float*)d_in[8];
    const float* wo = (const float*)d_in[9];
    const float* bo = (const float*)d_in[10];
    float* out = (float*)d_out;

    float *qp, *kp, *vp, *vtp, *ap;
    cudaGetSymbolAddress((void**)&qp,  g_q);
    cudaGetSymbolAddress((void**)&kp,  g_k);
    cudaGetSymbolAddress((void**)&vp,  g_v);
    cudaGetSymbolAddress((void**)&vtp, g_vt);
    cudaGetSymbolAddress((void**)&ap,  g_attn);

    cudaFuncSetAttribute(attn_mma_kernel,
                         cudaFuncAttributeMaxDynamicSharedMemorySize, ATT_SMEM);

    build_tables_kernel<<<(SEQL * 32 + 255) / 256, 256>>>();

    dim3 gg(EMB / 128, MTOT / 128);  // (8, 64)
    const float scaling = 0.125f;    // HD^-0.5
    gemm_mma_kernel<<<gg, 256>>>(query, wq, bq, qp, scaling);
    gemm_mma_kernel<<<gg, 256>>>(key_,  wk, bk, kp, 1.0f);
    gemm_mma_kernel<<<gg, 256>>>(value, wv, bv, vp, 1.0f);

    transpose_v_kernel<<<dim3(SEQL / 32, HD / 32, BSZ * NH), 256>>>(vp, vtp);

    attn_mma_kernel<<<dim3(BSZ * NH, SEQL / 128), 256, ATT_SMEM>>>(qp, kp, vtp, ap);

    gemm_mma_kernel<<<gg, 256>>>(ap, wo, bo, out, 1.0f);
}

// round 6
// speedup vs baseline: 2.9263x; 1.1555x over previous
#include <cuda_runtime.h>
#include <cstdint>
#include <math.h>

#define BSZ  8
#define SEQL 1024
#define EMB  1024
#define NH   16
#define HD   64
#define MTOT (BSZ * SEQL)   // 8192

// ---------------- scratch (device globals; no allocations allowed) ----------
__device__ float g_q[MTOT * EMB];
__device__ float g_k[MTOT * EMB];
__device__ float g_v[MTOT * EMB];
__device__ float g_vt[BSZ * NH * HD * SEQL];   // V^T per (b,h): [bh][d][t]
__device__ float g_attn[MTOT * EMB];
__device__ float g_cq[SEQL * 32];
__device__ float g_sq[SEQL * 32];
__device__ float g_ck[SEQL * 32];
__device__ float g_sk[SEQL * 32];

// ---------------- xpos cos/sin * scale tables --------------------------------
__global__ void build_tables_kernel() {
    int idx = blockIdx.x * blockDim.x + threadIdx.x;
    if (idx >= SEQL * 32) return;
    int t = idx >> 5;
    int i = idx & 31;
    float s_i   = (2.0f * (float)i + 0.4f * (float)HD) / (1.4f * (float)HD);
    float pos   = (float)t - (float)(SEQL / 2);
    float scale = powf(s_i, pos / (float)EMB);
    float invf  = powf(10000.0f, -(float)i / (float)(HD / 2));
    float sn, cs;
    sincosf((float)t * invf, &sn, &cs);
    g_cq[idx] = cs * scale;
    g_sq[idx] = sn * scale;
    g_ck[idx] = cs / scale;
    g_sk[idx] = sn / scale;
}

// ---------------- tf32 helpers ------------------------------------------------
static __device__ __forceinline__ uint32_t f2tf32(float f) {
    uint32_t u;
    asm("cvt.rna.tf32.f32 %0, %1;" : "=r"(u) : "f"(f));
    return u;
}

#define MMA_TF32(c, a, b) \
    asm volatile("mma.sync.aligned.m16n8k8.row.col.f32.tf32.tf32.f32 " \
        "{%0,%1,%2,%3}, {%4,%5,%6,%7}, {%8,%9}, {%0,%1,%2,%3};" \
        : "+f"((c)[0]), "+f"((c)[1]), "+f"((c)[2]), "+f"((c)[3]) \
        : "r"((a)[0]), "r"((a)[1]), "r"((a)[2]), "r"((a)[3]), \
          "r"((b)[0]), "r"((b)[1]))

// ---------------- fused QKV / generic GEMM body --------------------------------
// C = alpha * (A @ W^T + bias); R4 scalar-LDS layout, single sync per k-iter.
#define KC 16
#define KPAD 20

struct GemmArgs {
    const float* A; const float* W; const float* bias; float* C; float alpha;
};

static __device__ __forceinline__ void gemm_body(
    const float* __restrict__ A, const float* __restrict__ W,
    const float* __restrict__ bias, float* __restrict__ C, float alpha,
    uint32_t (*As)[128][KPAD], uint32_t (*Ws)[128][KPAD],
    int m0, int n0)
{
    const int tid  = threadIdx.x;
    const int lane = tid & 31;
    const int wid  = tid >> 5;
    const int wm = (wid >> 2) << 6;
    const int wn = (wid & 3) << 5;

    const int fm = tid >> 1;
    const int fk = (tid & 1) << 3;
    const float* Ap = A + (size_t)(m0 + fm) * EMB + fk;
    const float* Wp = W + (size_t)(n0 + fm) * EMB + fk;

    uint32_t ra[8], rw[8];
    auto fetch = [&](int k0) {
        float4 a0 = *(const float4*)(Ap + k0);
        float4 a1 = *(const float4*)(Ap + k0 + 4);
        float4 w0 = *(const float4*)(Wp + k0);
        float4 w1 = *(const float4*)(Wp + k0 + 4);
        ra[0] = f2tf32(a0.x); ra[1] = f2tf32(a0.y); ra[2] = f2tf32(a0.z); ra[3] = f2tf32(a0.w);
        ra[4] = f2tf32(a1.x); ra[5] = f2tf32(a1.y); ra[6] = f2tf32(a1.z); ra[7] = f2tf32(a1.w);
        rw[0] = f2tf32(w0.x); rw[1] = f2tf32(w0.y); rw[2] = f2tf32(w0.z); rw[3] = f2tf32(w0.w);
        rw[4] = f2tf32(w1.x); rw[5] = f2tf32(w1.y); rw[6] = f2tf32(w1.z); rw[7] = f2tf32(w1.w);
    };
    auto stbuf = [&](int b) {
        *(uint4*)&As[b][fm][fk]     = make_uint4(ra[0], ra[1], ra[2], ra[3]);
        *(uint4*)&As[b][fm][fk + 4] = make_uint4(ra[4], ra[5], ra[6], ra[7]);
        *(uint4*)&Ws[b][fm][fk]     = make_uint4(rw[0], rw[1], rw[2], rw[3]);
        *(uint4*)&Ws[b][fm][fk + 4] = make_uint4(rw[4], rw[5], rw[6], rw[7]);
    };

    fetch(0);
    stbuf(0);

    float c[4][4][4];
#pragma unroll
    for (int mf = 0; mf < 4; mf++)
#pragma unroll
        for (int nf = 0; nf < 4; nf++)
#pragma unroll
            for (int q = 0; q < 4; q++) c[mf][nf][q] = 0.0f;

    const int NK = EMB / KC;
    const int qrow = lane >> 2;
    const int qcol = lane & 3;

    for (int kt = 0; kt < NK; kt++) {
        const int b = kt & 1;
        __syncthreads();
        if (kt + 1 < NK) fetch((kt + 1) * KC);

#pragma unroll
        for (int k8 = 0; k8 < KC; k8 += 8) {
            uint32_t af[4][4], bf[4][2];
#pragma unroll
            for (int mf = 0; mf < 4; mf++) {
                int r = wm + (mf << 4) + qrow;
                af[mf][0] = As[b][r][k8 + qcol];
                af[mf][1] = As[b][r + 8][k8 + qcol];
                af[mf][2] = As[b][r][k8 + qcol + 4];
                af[mf][3] = As[b][r + 8][k8 + qcol + 4];
            }
#pragma unroll
            for (int nf = 0; nf < 4; nf++) {
                int n = wn + (nf << 3) + qrow;
                bf[nf][0] = Ws[b][n][k8 + qcol];
                bf[nf][1] = Ws[b][n][k8 + qcol + 4];
            }
#pragma unroll
            for (int mf = 0; mf < 4; mf++)
#pragma unroll
                for (int nf = 0; nf < 4; nf++)
                    MMA_TF32(c[mf][nf], af[mf], bf[nf]);
        }
        if (kt + 1 < NK) stbuf(b ^ 1);
    }

#pragma unroll
    for (int mf = 0; mf < 4; mf++) {
        int r0 = m0 + wm + (mf << 4) + qrow;
#pragma unroll
        for (int nf = 0; nf < 4; nf++) {
            int cb = n0 + wn + (nf << 3) + (qcol << 1);
            float2 bv = *(const float2*)(bias + cb);
            float2 o0, o1;
            o0.x = alpha * (c[mf][nf][0] + bv.x);
            o0.y = alpha * (c[mf][nf][1] + bv.y);
            o1.x = alpha * (c[mf][nf][2] + bv.x);
            o1.y = alpha * (c[mf][nf][3] + bv.y);
            *(float2*)(C + (size_t)r0 * EMB + cb)       = o0;
            *(float2*)(C + (size_t)(r0 + 8) * EMB + cb) = o1;
        }
    }
}

// merged QKV: blockIdx.z selects {query->g_q, key->g_k, value->g_v}
__global__ __launch_bounds__(256, 2) void gemm_qkv_kernel(
    const float* __restrict__ query, const float* __restrict__ key_,
    const float* __restrict__ value,
    const float* __restrict__ wq, const float* __restrict__ bq,
    const float* __restrict__ wk, const float* __restrict__ bk,
    const float* __restrict__ wv, const float* __restrict__ bv,
    float* __restrict__ Cq, float* __restrict__ Ck, float* __restrict__ Cv,
    float alpha_q)
{
    __shared__ __align__(16) uint32_t As[2][128][KPAD];
    __shared__ __align__(16) uint32_t Ws[2][128][KPAD];
    const int z = blockIdx.z;
    const float* A    = (z == 0) ? query : (z == 1) ? key_ : value;
    const float* W    = (z == 0) ? wq : (z == 1) ? wk : wv;
    const float* bias = (z == 0) ? bq : (z == 1) ? bk : bv;
    float* C          = (z == 0) ? Cq : (z == 1) ? Ck : Cv;
    float alpha       = (z == 0) ? alpha_q : 1.0f;
    gemm_body(A, W, bias, C, alpha, As, Ws, blockIdx.y << 7, blockIdx.x << 7);
}

__global__ __launch_bounds__(256, 2) void gemm_mma_kernel(
    const float* __restrict__ A, const float* __restrict__ W,
    const float* __restrict__ bias, float* __restrict__ C, float alpha)
{
    __shared__ __align__(16) uint32_t As[2][128][KPAD];
    __shared__ __align__(16) uint32_t Ws[2][128][KPAD];
    gemm_body(A, W, bias, C, alpha, As, Ws, blockIdx.y << 7, blockIdx.x << 7);
}

// ---------------- V transpose: g_v [b*1024+t][h*64+d] -> g_vt [bh][d][t] ------
__global__ __launch_bounds__(256) void transpose_v_kernel(
    const float* __restrict__ V, float* __restrict__ VT)
{
    __shared__ float tile[32][33];
    const int t0 = blockIdx.x << 5;
    const int d0 = blockIdx.y << 5;
    const int bh = blockIdx.z;
    const int b  = bh >> 4;
    const int h  = bh & 15;
    const int txx = threadIdx.x & 31;
    const int tyy = threadIdx.x >> 5;
#pragma unroll
    for (int i = 0; i < 4; i++) {
        int t = t0 + tyy + (i << 3);
        tile[tyy + (i << 3)][txx] =
            V[(size_t)(b * SEQL + t) * EMB + h * HD + d0 + txx];
    }
    __syncthreads();
#pragma unroll
    for (int i = 0; i < 4; i++) {
        int d = d0 + tyy + (i << 3);
        VT[(size_t)(bh * HD + d) * SEQL + t0 + txx] = tile[txx][tyy + (i << 3)];
    }
}

// ---------------- tensor-core flash attention ---------------------------------
#define ATT_SMEM ((128 + 128 + 64 + 64) * 68 * 4)

static __device__ __forceinline__ int kperm(int k) {
    return (k & ~7) | ((k & 3) << 1) | ((k >> 2) & 1);
}

__global__ __launch_bounds__(256) void attn_mma_kernel(
    const float* __restrict__ Q, const float* __restrict__ K,
    const float* __restrict__ VT, float* __restrict__ O)
{
    extern __shared__ __align__(16) uint32_t dsm[];
    uint32_t (*Qs)[68] = (uint32_t(*)[68])dsm;
    uint32_t (*Ps)[68] = (uint32_t(*)[68])(dsm + 128 * 68);
    uint32_t (*Ks)[68] = (uint32_t(*)[68])(dsm + 256 * 68);
    uint32_t (*Vt)[68] = (uint32_t(*)[68])(dsm + 320 * 68);

    const int tid  = threadIdx.x;
    const int lane = tid & 31;
    const int wid  = tid >> 5;
    const int u = lane >> 2;
    const int v = lane & 3;
    const int W = wid << 4;

    const int bh = blockIdx.x;
    const int qt = blockIdx.y;
    const int b  = bh >> 4;
    const int h  = bh & 15;

    const float* qb = Q + ((size_t)(b * SEQL) + qt * 128) * EMB + h * HD;
    const float* kb = K + (size_t)(b * SEQL) * EMB + h * HD;
    const float* vtb = VT + (size_t)bh * HD * SEQL;
    float* ob = O + ((size_t)(b * SEQL) + qt * 128) * EMB + h * HD;

#pragma unroll
    for (int it = 0; it < 8; it++) {
        int f  = tid + (it << 8);
        int r  = f >> 4;
        int tx = f & 15;
        int t  = qt * 128 + r;
        float4 x = *(const float4*)(qb + (size_t)r * EMB + (tx << 2));
        float2 c0 = *(const float2*)(g_cq + t * 32 + (tx << 1));
        float2 s0 = *(const float2*)(g_sq + t * 32 + (tx << 1));
        float y0 = x.x * c0.x - x.y * s0.x;
        float y1 = x.y * c0.x + x.x * s0.x;
        float y2 = x.z * c0.y - x.w * s0.y;
        float y3 = x.w * c0.y + x.z * s0.y;
        int base = (tx >> 1) << 3;
        int hi   = tx & 1;
        Qs[r][base + 0 + hi] = f2tf32(y0);
        Qs[r][base + 2 + hi] = f2tf32(y1);
        Qs[r][base + 4 + hi] = f2tf32(y2);
        Qs[r][base + 6 + hi] = f2tf32(y3);
    }

    float o[8][4];
    float m0 = -INFINITY, m1 = -INFINITY, l0 = 0.0f, l1 = 0.0f;
#pragma unroll
    for (int nf = 0; nf < 8; nf++)
#pragma unroll
        for (int q = 0; q < 4; q++) o[nf][q] = 0.0f;

    for (int kt = 0; kt < SEQL / 64; kt++) {
        __syncthreads();
#pragma unroll
        for (int it = 0; it < 4; it++) {
            int f  = tid + (it << 8);
            int r  = f >> 4;
            int tx = f & 15;
            int t  = kt * 64 + r;
            float4 x = *(const float4*)(kb + (size_t)t * EMB + (tx << 2));
            float2 c0 = *(const float2*)(g_ck + t * 32 + (tx << 1));
            float2 s0 = *(const float2*)(g_sk + t * 32 + (tx << 1));
            float y0 = x.x * c0.x - x.y * s0.x;
            float y1 = x.y * c0.x + x.x * s0.x;
            float y2 = x.z * c0.y - x.w * s0.y;
            float y3 = x.w * c0.y + x.z * s0.y;
            int base = (tx >> 1) << 3;
            int hi   = tx & 1;
            Ks[r][base + 0 + hi] = f2tf32(y0);
            Ks[r][base + 2 + hi] = f2tf32(y1);
            Ks[r][base + 4 + hi] = f2tf32(y2);
            Ks[r][base + 6 + hi] = f2tf32(y3);
            float4 vv = *(const float4*)(vtb + (size_t)r * SEQL + kt * 64 + (tx << 2));
            Vt[r][base + 0 + hi] = f2tf32(vv.x);
            Vt[r][base + 2 + hi] = f2tf32(vv.y);
            Vt[r][base + 4 + hi] = f2tf32(vv.z);
            Vt[r][base + 6 + hi] = f2tf32(vv.w);
        }
        __syncthreads();

        float s[8][4];
#pragma unroll
        for (int nf = 0; nf < 8; nf++)
#pragma unroll
            for (int q = 0; q < 4; q++) s[nf][q] = 0.0f;
#pragma unroll
        for (int k8 = 0; k8 < 64; k8 += 8) {
            uint32_t af[4];
            uint2 a0 = *(uint2*)&Qs[W + u][k8 + 2 * v];
            uint2 a1 = *(uint2*)&Qs[W + u + 8][k8 + 2 * v];
            af[0] = a0.x; af[1] = a1.x; af[2] = a0.y; af[3] = a1.y;
#pragma unroll
            for (int nf = 0; nf < 8; nf++) {
                uint2 bq = *(uint2*)&Ks[(nf << 3) + u][k8 + 2 * v];
                uint32_t bf[2] = {bq.x, bq.y};
                MMA_TF32(s[nf], af, bf);
            }
        }

        float mx0 = -INFINITY, mx1 = -INFINITY;
#pragma unroll
        for (int nf = 0; nf < 8; nf++) {
            mx0 = fmaxf(mx0, fmaxf(s[nf][0], s[nf][1]));
            mx1 = fmaxf(mx1, fmaxf(s[nf][2], s[nf][3]));
        }
        mx0 = fmaxf(mx0, __shfl_xor_sync(0xffffffffu, mx0, 1));
        mx0 = fmaxf(mx0, __shfl_xor_sync(0xffffffffu, mx0, 2));
        mx1 = fmaxf(mx1, __shfl_xor_sync(0xffffffffu, mx1, 1));
        mx1 = fmaxf(mx1, __shfl_xor_sync(0xffffffffu, mx1, 2));
        float nm0 = fmaxf(m0, mx0), nm1 = fmaxf(m1, mx1);
        float al0 = __expf(m0 - nm0), al1 = __expf(m1 - nm1);
        float ts0 = 0.0f, ts1 = 0.0f;
#pragma unroll
        for (int nf = 0; nf < 8; nf++) {
            s[nf][0] = __expf(s[nf][0] - nm0);
            s[nf][1] = __expf(s[nf][1] - nm0);
            s[nf][2] = __expf(s[nf][2] - nm1);
            s[nf][3] = __expf(s[nf][3] - nm1);
            ts0 += s[nf][0] + s[nf][1];
            ts1 += s[nf][2] + s[nf][3];
        }
        ts0 += __shfl_xor_sync(0xffffffffu, ts0, 1);
        ts0 += __shfl_xor_sync(0xffffffffu, ts0, 2);
        ts1 += __shfl_xor_sync(0xffffffffu, ts1, 1);
        ts1 += __shfl_xor_sync(0xffffffffu, ts1, 2);
        l0 = l0 * al0 + ts0; l1 = l1 * al1 + ts1;
        m0 = nm0; m1 = nm1;
#pragma unroll
        for (int nf = 0; nf < 8; nf++) {
            o[nf][0] *= al0; o[nf][1] *= al0;
            o[nf][2] *= al1; o[nf][3] *= al1;
        }

#pragma unroll
        for (int nf = 0; nf < 8; nf++) {
            int col = (nf << 3) + (v << 1);
            int pp  = kperm(col);
            Ps[W + u][pp]         = f2tf32(s[nf][0]);
            Ps[W + u][pp + 2]     = f2tf32(s[nf][1]);
            Ps[W + u + 8][pp]     = f2tf32(s[nf][2]);
            Ps[W + u + 8][pp + 2] = f2tf32(s[nf][3]);
        }
        __syncthreads();

#pragma unroll
        for (int k8 = 0; k8 < 64; k8 += 8) {
            uint32_t af[4];
            uint2 a0 = *(uint2*)&Ps[W + u][k8 + 2 * v];
            uint2 a1 = *(uint2*)&Ps[W + u + 8][k8 + 2 * v];
            af[0] = a0.x; af[1] = a1.x; af[2] = a0.y; af[3] = a1.y;
#pragma unroll
            for (int nf = 0; nf < 8; nf++) {
                uint2 bq = *(uint2*)&Vt[(nf << 3) + u][k8 + 2 * v];
                uint32_t bf[2] = {bq.x, bq.y};
                MMA_TF32(o[nf], af, bf);
            }
        }
    }

    float inv0 = 1.0f / l0, inv1 = 1.0f / l1;
#pragma unroll
    for (int nf = 0; nf < 8; nf++) {
        int cb = (nf << 3) + (v << 1);
        float2 w0 = {o[nf][0] * inv0, o[nf][1] * inv0};
        float2 w1 = {o[nf][2] * inv1, o[nf][3] * inv1};
        *(float2*)(ob + (size_t)(W + u) * EMB + cb)     = w0;
        *(float2*)(ob + (size_t)(W + u + 8) * EMB + cb) = w1;
    }
}

// ---------------- launch ------------------------------------------------------
extern "C" void kernel_launch(void* const* d_in, const int* in_sizes, int n_in,
                              void* d_out, int out_size) {
    const float* query = (const float*)d_in[0];
    const float* key_  = (const float*)d_in[1];
    const float* value = (const float*)d_in[2];
    const float* wq = (const float*)d_in[3];
    const float* bq = (const float*)d_in[4];
    const float* wk = (const float*)d_in[5];
    const float* bk = (const float*)d_in[6];
    const float* wv = (const float*)d_in[7];
    const float* bv = (const float*)d_in[8];
    const float* wo = (const float*)d_in[9];
    const float* bo = (const float*)d_in[10];
    float* out = (float*)d_out;

    float *qp, *kp, *vp, *vtp, *ap;
    cudaGetSymbolAddress((void**)&qp,  g_q);
    cudaGetSymbolAddress((void**)&kp,  g_k);
    cudaGetSymbolAddress((void**)&vp,  g_v);
    cudaGetSymbolAddress((void**)&vtp, g_vt);
    cudaGetSymbolAddress((void**)&ap,  g_attn);

    cudaFuncSetAttribute(attn_mma_kernel,
                         cudaFuncAttributeMaxDynamicSharedMemorySize, ATT_SMEM);

    build_tables_kernel<<<(SEQL * 32 + 255) / 256, 256>>>();

    const float scaling = 0.125f;    // HD^-0.5
    gemm_qkv_kernel<<<dim3(EMB / 128, MTOT / 128, 3), 256>>>(
        query, key_, value, wq, bq, wk, bk, wv, bv, qp, kp, vp, scaling);

    transpose_v_kernel<<<dim3(SEQL / 32, HD / 32, BSZ * NH), 256>>>(vp, vtp);

    attn_mma_kernel<<<dim3(BSZ * NH, SEQL / 128), 256, ATT_SMEM>>>(qp, kp, vtp, ap);

    gemm_mma_kernel<<<dim3(EMB / 128, MTOT / 128), 256>>>(ap, wo, bo, out, 1.0f);
}

// round 7
// speedup vs baseline: 3.2977x; 1.1269x over previous
#include <cuda_runtime.h>
#include <cstdint>
#include <math.h>

#define BSZ  8
#define SEQL 1024
#define EMB  1024
#define NH   16
#define HD   64
#define MTOT (BSZ * SEQL)   // 8192

// ---------------- scratch (device globals; no allocations allowed) ----------
__device__ float g_q[MTOT * EMB];
__device__ float g_k[MTOT * EMB];
__device__ float g_v[MTOT * EMB];
__device__ float g_vt[BSZ * NH * HD * SEQL];   // V^T per (b,h): [bh][d][t]
__device__ float g_attn[MTOT * EMB];
__device__ float g_cq[SEQL * 32];
__device__ float g_sq[SEQL * 32];
__device__ float g_ck[SEQL * 32];
__device__ float g_sk[SEQL * 32];

// ---------------- xpos cos/sin * scale tables --------------------------------
__global__ void build_tables_kernel() {
    int idx = blockIdx.x * blockDim.x + threadIdx.x;
    if (idx >= SEQL * 32) return;
    int t = idx >> 5;
    int i = idx & 31;
    float s_i   = (2.0f * (float)i + 0.4f * (float)HD) / (1.4f * (float)HD);
    float pos   = (float)t - (float)(SEQL / 2);
    float scale = powf(s_i, pos / (float)EMB);
    float invf  = powf(10000.0f, -(float)i / (float)(HD / 2));
    float sn, cs;
    sincosf((float)t * invf, &sn, &cs);
    g_cq[idx] = cs * scale;
    g_sq[idx] = sn * scale;
    g_ck[idx] = cs / scale;
    g_sk[idx] = sn / scale;
}

// ---------------- tf32 helpers ------------------------------------------------
static __device__ __forceinline__ uint32_t f2tf32(float f) {
    uint32_t u;
    asm("cvt.rna.tf32.f32 %0, %1;" : "=r"(u) : "f"(f));
    return u;
}

#define MMA_TF32(c, a, b) \
    asm volatile("mma.sync.aligned.m16n8k8.row.col.f32.tf32.tf32.f32 " \
        "{%0,%1,%2,%3}, {%4,%5,%6,%7}, {%8,%9}, {%0,%1,%2,%3};" \
        : "+f"((c)[0]), "+f"((c)[1]), "+f"((c)[2]), "+f"((c)[3]) \
        : "r"((a)[0]), "r"((a)[1]), "r"((a)[2]), "r"((a)[3]), \
          "r"((b)[0]), "r"((b)[1]))

// ---------------- fused QKV / generic GEMM body --------------------------------
#define KC 16
#define KPAD 20

static __device__ __forceinline__ void gemm_body(
    const float* __restrict__ A, const float* __restrict__ W,
    const float* __restrict__ bias, float* __restrict__ C, float alpha,
    uint32_t (*As)[128][KPAD], uint32_t (*Ws)[128][KPAD],
    int m0, int n0)
{
    const int tid  = threadIdx.x;
    const int lane = tid & 31;
    const int wid  = tid >> 5;
    const int wm = (wid >> 2) << 6;
    const int wn = (wid & 3) << 5;

    const int fm = tid >> 1;
    const int fk = (tid & 1) << 3;
    const float* Ap = A + (size_t)(m0 + fm) * EMB + fk;
    const float* Wp = W + (size_t)(n0 + fm) * EMB + fk;

    uint32_t ra[8], rw[8];
    auto fetch = [&](int k0) {
        float4 a0 = *(const float4*)(Ap + k0);
        float4 a1 = *(const float4*)(Ap + k0 + 4);
        float4 w0 = *(const float4*)(Wp + k0);
        float4 w1 = *(const float4*)(Wp + k0 + 4);
        ra[0] = f2tf32(a0.x); ra[1] = f2tf32(a0.y); ra[2] = f2tf32(a0.z); ra[3] = f2tf32(a0.w);
        ra[4] = f2tf32(a1.x); ra[5] = f2tf32(a1.y); ra[6] = f2tf32(a1.z); ra[7] = f2tf32(a1.w);
        rw[0] = f2tf32(w0.x); rw[1] = f2tf32(w0.y); rw[2] = f2tf32(w0.z); rw[3] = f2tf32(w0.w);
        rw[4] = f2tf32(w1.x); rw[5] = f2tf32(w1.y); rw[6] = f2tf32(w1.z); rw[7] = f2tf32(w1.w);
    };
    auto stbuf = [&](int b) {
        *(uint4*)&As[b][fm][fk]     = make_uint4(ra[0], ra[1], ra[2], ra[3]);
        *(uint4*)&As[b][fm][fk + 4] = make_uint4(ra[4], ra[5], ra[6], ra[7]);
        *(uint4*)&Ws[b][fm][fk]     = make_uint4(rw[0], rw[1], rw[2], rw[3]);
        *(uint4*)&Ws[b][fm][fk + 4] = make_uint4(rw[4], rw[5], rw[6], rw[7]);
    };

    fetch(0);
    stbuf(0);

    float c[4][4][4];
#pragma unroll
    for (int mf = 0; mf < 4; mf++)
#pragma unroll
        for (int nf = 0; nf < 4; nf++)
#pragma unroll
            for (int q = 0; q < 4; q++) c[mf][nf][q] = 0.0f;

    const int NK = EMB / KC;
    const int qrow = lane >> 2;
    const int qcol = lane & 3;

    for (int kt = 0; kt < NK; kt++) {
        const int b = kt & 1;
        __syncthreads();
        if (kt + 1 < NK) fetch((kt + 1) * KC);

#pragma unroll
        for (int k8 = 0; k8 < KC; k8 += 8) {
            uint32_t af[4][4], bf[4][2];
#pragma unroll
            for (int mf = 0; mf < 4; mf++) {
                int r = wm + (mf << 4) + qrow;
                af[mf][0] = As[b][r][k8 + qcol];
                af[mf][1] = As[b][r + 8][k8 + qcol];
                af[mf][2] = As[b][r][k8 + qcol + 4];
                af[mf][3] = As[b][r + 8][k8 + qcol + 4];
            }
#pragma unroll
            for (int nf = 0; nf < 4; nf++) {
                int n = wn + (nf << 3) + qrow;
                bf[nf][0] = Ws[b][n][k8 + qcol];
                bf[nf][1] = Ws[b][n][k8 + qcol + 4];
            }
#pragma unroll
            for (int mf = 0; mf < 4; mf++)
#pragma unroll
                for (int nf = 0; nf < 4; nf++)
                    MMA_TF32(c[mf][nf], af[mf], bf[nf]);
        }
        if (kt + 1 < NK) stbuf(b ^ 1);
    }

#pragma unroll
    for (int mf = 0; mf < 4; mf++) {
        int r0 = m0 + wm + (mf << 4) + qrow;
#pragma unroll
        for (int nf = 0; nf < 4; nf++) {
            int cb = n0 + wn + (nf << 3) + (qcol << 1);
            float2 bv = *(const float2*)(bias + cb);
            float2 o0, o1;
            o0.x = alpha * (c[mf][nf][0] + bv.x);
            o0.y = alpha * (c[mf][nf][1] + bv.y);
            o1.x = alpha * (c[mf][nf][2] + bv.x);
            o1.y = alpha * (c[mf][nf][3] + bv.y);
            *(float2*)(C + (size_t)r0 * EMB + cb)       = o0;
            *(float2*)(C + (size_t)(r0 + 8) * EMB + cb) = o1;
        }
    }
}

__global__ __launch_bounds__(256, 2) void gemm_qkv_kernel(
    const float* __restrict__ query, const float* __restrict__ key_,
    const float* __restrict__ value,
    const float* __restrict__ wq, const float* __restrict__ bq,
    const float* __restrict__ wk, const float* __restrict__ bk,
    const float* __restrict__ wv, const float* __restrict__ bv,
    float* __restrict__ Cq, float* __restrict__ Ck, float* __restrict__ Cv,
    float alpha_q)
{
    __shared__ __align__(16) uint32_t As[2][128][KPAD];
    __shared__ __align__(16) uint32_t Ws[2][128][KPAD];
    const int z = blockIdx.z;
    const float* A    = (z == 0) ? query : (z == 1) ? key_ : value;
    const float* W    = (z == 0) ? wq : (z == 1) ? wk : wv;
    const float* bias = (z == 0) ? bq : (z == 1) ? bk : bv;
    float* C          = (z == 0) ? Cq : (z == 1) ? Ck : Cv;
    float alpha       = (z == 0) ? alpha_q : 1.0f;
    gemm_body(A, W, bias, C, alpha, As, Ws, blockIdx.y << 7, blockIdx.x << 7);
}

__global__ __launch_bounds__(256, 2) void gemm_mma_kernel(
    const float* __restrict__ A, const float* __restrict__ W,
    const float* __restrict__ bias, float* __restrict__ C, float alpha)
{
    __shared__ __align__(16) uint32_t As[2][128][KPAD];
    __shared__ __align__(16) uint32_t Ws[2][128][KPAD];
    gemm_body(A, W, bias, C, alpha, As, Ws, blockIdx.y << 7, blockIdx.x << 7);
}

// ---------------- V transpose: g_v [b*1024+t][h*64+d] -> g_vt [bh][d][t] ------
__global__ __launch_bounds__(256) void transpose_v_kernel(
    const float* __restrict__ V, float* __restrict__ VT)
{
    __shared__ float tile[32][33];
    const int t0 = blockIdx.x << 5;
    const int d0 = blockIdx.y << 5;
    const int bh = blockIdx.z;
    const int b  = bh >> 4;
    const int h  = bh & 15;
    const int txx = threadIdx.x & 31;
    const int tyy = threadIdx.x >> 5;
#pragma unroll
    for (int i = 0; i < 4; i++) {
        int t = t0 + tyy + (i << 3);
        tile[tyy + (i << 3)][txx] =
            V[(size_t)(b * SEQL + t) * EMB + h * HD + d0 + txx];
    }
    __syncthreads();
#pragma unroll
    for (int i = 0; i < 4; i++) {
        int d = d0 + tyy + (i << 3);
        VT[(size_t)(bh * HD + d) * SEQL + t0 + txx] = tile[txx][tyy + (i << 3)];
    }
}

// ---------------- tensor-core flash attention ---------------------------------
// 128 threads (4 warps); warp owns 32 q-rows (2 m16 tiles).
// P kept in registers; S-accum -> A-frag via shfl. Row stride 72 (conflict-free
// uint2 fragment loads: 8u+2v distinct per half-warp phase).
#define AST 72
#define ATT_SMEM ((128 + 64 + 64) * AST * 4)

__global__ __launch_bounds__(128) void attn_mma_kernel(
    const float* __restrict__ Q, const float* __restrict__ K,
    const float* __restrict__ VT, float* __restrict__ O)
{
    extern __shared__ __align__(16) uint32_t dsm[];
    uint32_t (*Qs)[AST] = (uint32_t(*)[AST])dsm;
    uint32_t (*Ks)[AST] = (uint32_t(*)[AST])(dsm + 128 * AST);
    uint32_t (*Vt)[AST] = (uint32_t(*)[AST])(dsm + 192 * AST);

    const int tid  = threadIdx.x;
    const int lane = tid & 31;
    const int wid  = tid >> 5;
    const int u = lane >> 2;
    const int v = lane & 3;
    const int W = wid << 5;               // warp q base (32 rows)
    const int src0 = (lane & 28) | (v >> 1);
    const int src1 = src0 + 2;
    const bool odd = v & 1;

    const int bh = blockIdx.x;
    const int qt = blockIdx.y;
    const int b  = bh >> 4;
    const int h  = bh & 15;

    const float* qb = Q + ((size_t)(b * SEQL) + qt * 128) * EMB + h * HD;
    const float* kb = K + (size_t)(b * SEQL) * EMB + h * HD;
    const float* vtb = VT + (size_t)bh * HD * SEQL;
    float* ob = O + ((size_t)(b * SEQL) + qt * 128) * EMB + h * HD;

    // ---- fill Q (once), xpos upscale, permuted cols ----
#pragma unroll
    for (int it = 0; it < 16; it++) {
        int f  = tid + (it << 7);
        int r  = f >> 4;
        int tx = f & 15;
        int t  = qt * 128 + r;
        float4 x = *(const float4*)(qb + (size_t)r * EMB + (tx << 2));
        float2 c0 = *(const float2*)(g_cq + t * 32 + (tx << 1));
        float2 s0 = *(const float2*)(g_sq + t * 32 + (tx << 1));
        float y0 = x.x * c0.x - x.y * s0.x;
        float y1 = x.y * c0.x + x.x * s0.x;
        float y2 = x.z * c0.y - x.w * s0.y;
        float y3 = x.w * c0.y + x.z * s0.y;
        int base = (tx >> 1) << 3;
        int hi   = tx & 1;
        Qs[r][base + 0 + hi] = f2tf32(y0);
        Qs[r][base + 2 + hi] = f2tf32(y1);
        Qs[r][base + 4 + hi] = f2tf32(y2);
        Qs[r][base + 6 + hi] = f2tf32(y3);
    }

    float o[2][8][4];
    float mm[2][2], ll[2][2];
#pragma unroll
    for (int mt = 0; mt < 2; mt++) {
        mm[mt][0] = -INFINITY; mm[mt][1] = -INFINITY;
        ll[mt][0] = 0.0f;      ll[mt][1] = 0.0f;
#pragma unroll
        for (int nf = 0; nf < 8; nf++)
#pragma unroll
            for (int q = 0; q < 4; q++) o[mt][nf][q] = 0.0f;
    }

    for (int kt = 0; kt < SEQL / 64; kt++) {
        __syncthreads();   // prev iter done reading Ks/Vt
        // ---- fill K (xpos downscale) + Vt ----
#pragma unroll
        for (int it = 0; it < 8; it++) {
            int f  = tid + (it << 7);
            int r  = f >> 4;
            int tx = f & 15;
            int t  = kt * 64 + r;
            float4 x = *(const float4*)(kb + (size_t)t * EMB + (tx << 2));
            float2 c0 = *(const float2*)(g_ck + t * 32 + (tx << 1));
            float2 s0 = *(const float2*)(g_sk + t * 32 + (tx << 1));
            float y0 = x.x * c0.x - x.y * s0.x;
            float y1 = x.y * c0.x + x.x * s0.x;
            float y2 = x.z * c0.y - x.w * s0.y;
            float y3 = x.w * c0.y + x.z * s0.y;
            int base = (tx >> 1) << 3;
            int hi   = tx & 1;
            Ks[r][base + 0 + hi] = f2tf32(y0);
            Ks[r][base + 2 + hi] = f2tf32(y1);
            Ks[r][base + 4 + hi] = f2tf32(y2);
            Ks[r][base + 6 + hi] = f2tf32(y3);
            float4 vv = *(const float4*)(vtb + (size_t)r * SEQL + kt * 64 + (tx << 2));
            Vt[r][base + 0 + hi] = f2tf32(vv.x);
            Vt[r][base + 2 + hi] = f2tf32(vv.y);
            Vt[r][base + 4 + hi] = f2tf32(vv.z);
            Vt[r][base + 6 + hi] = f2tf32(vv.w);
        }
        __syncthreads();

        // ---- S = Q @ K^T  (2 m-tiles share each K fragment) ----
        float s[2][8][4];
#pragma unroll
        for (int mt = 0; mt < 2; mt++)
#pragma unroll
            for (int nf = 0; nf < 8; nf++)
#pragma unroll
                for (int q = 0; q < 4; q++) s[mt][nf][q] = 0.0f;
#pragma unroll
        for (int k8 = 0; k8 < 64; k8 += 8) {
            uint32_t af[2][4];
            uint2 a0 = *(uint2*)&Qs[W + u][k8 + 2 * v];
            uint2 a1 = *(uint2*)&Qs[W + u + 8][k8 + 2 * v];
            uint2 a2 = *(uint2*)&Qs[W + 16 + u][k8 + 2 * v];
            uint2 a3 = *(uint2*)&Qs[W + 24 + u][k8 + 2 * v];
            af[0][0] = a0.x; af[0][1] = a1.x; af[0][2] = a0.y; af[0][3] = a1.y;
            af[1][0] = a2.x; af[1][1] = a3.x; af[1][2] = a2.y; af[1][3] = a3.y;
#pragma unroll
            for (int nf = 0; nf < 8; nf++) {
                uint2 bq = *(uint2*)&Ks[(nf << 3) + u][k8 + 2 * v];
                uint32_t bf[2] = {bq.x, bq.y};
                MMA_TF32(s[0][nf], af[0], bf);
                MMA_TF32(s[1][nf], af[1], bf);
            }
        }

        // ---- online softmax per m-tile ----
#pragma unroll
        for (int mt = 0; mt < 2; mt++) {
            float mx0 = -INFINITY, mx1 = -INFINITY;
#pragma unroll
            for (int nf = 0; nf < 8; nf++) {
                mx0 = fmaxf(mx0, fmaxf(s[mt][nf][0], s[mt][nf][1]));
                mx1 = fmaxf(mx1, fmaxf(s[mt][nf][2], s[mt][nf][3]));
            }
            mx0 = fmaxf(mx0, __shfl_xor_sync(0xffffffffu, mx0, 1));
            mx0 = fmaxf(mx0, __shfl_xor_sync(0xffffffffu, mx0, 2));
            mx1 = fmaxf(mx1, __shfl_xor_sync(0xffffffffu, mx1, 1));
            mx1 = fmaxf(mx1, __shfl_xor_sync(0xffffffffu, mx1, 2));
            float nm0 = fmaxf(mm[mt][0], mx0), nm1 = fmaxf(mm[mt][1], mx1);
            float al0 = __expf(mm[mt][0] - nm0), al1 = __expf(mm[mt][1] - nm1);
            float ts0 = 0.0f, ts1 = 0.0f;
#pragma unroll
            for (int nf = 0; nf < 8; nf++) {
                s[mt][nf][0] = __expf(s[mt][nf][0] - nm0);
                s[mt][nf][1] = __expf(s[mt][nf][1] - nm0);
                s[mt][nf][2] = __expf(s[mt][nf][2] - nm1);
                s[mt][nf][3] = __expf(s[mt][nf][3] - nm1);
                ts0 += s[mt][nf][0] + s[mt][nf][1];
                ts1 += s[mt][nf][2] + s[mt][nf][3];
            }
            ts0 += __shfl_xor_sync(0xffffffffu, ts0, 1);
            ts0 += __shfl_xor_sync(0xffffffffu, ts0, 2);
            ts1 += __shfl_xor_sync(0xffffffffu, ts1, 1);
            ts1 += __shfl_xor_sync(0xffffffffu, ts1, 2);
            ll[mt][0] = ll[mt][0] * al0 + ts0;
            ll[mt][1] = ll[mt][1] * al1 + ts1;
            mm[mt][0] = nm0; mm[mt][1] = nm1;
#pragma unroll
            for (int nf = 0; nf < 8; nf++) {
                o[mt][nf][0] *= al0; o[mt][nf][1] *= al0;
                o[mt][nf][2] *= al1; o[mt][nf][3] *= al1;
            }
        }

        // ---- O += P @ V; A-frag from S-accum via shfl (no smem P) ----
#pragma unroll
        for (int kk = 0; kk < 8; kk++) {
            uint32_t pa[2][4];
#pragma unroll
            for (int mt = 0; mt < 2; mt++) {
                float t00 = __shfl_sync(0xffffffffu, s[mt][kk][0], src0);
                float t01 = __shfl_sync(0xffffffffu, s[mt][kk][1], src0);
                float t20 = __shfl_sync(0xffffffffu, s[mt][kk][2], src0);
                float t21 = __shfl_sync(0xffffffffu, s[mt][kk][3], src0);
                float u00 = __shfl_sync(0xffffffffu, s[mt][kk][0], src1);
                float u01 = __shfl_sync(0xffffffffu, s[mt][kk][1], src1);
                float u20 = __shfl_sync(0xffffffffu, s[mt][kk][2], src1);
                float u21 = __shfl_sync(0xffffffffu, s[mt][kk][3], src1);
                pa[mt][0] = f2tf32(odd ? t01 : t00);
                pa[mt][1] = f2tf32(odd ? t21 : t20);
                pa[mt][2] = f2tf32(odd ? u01 : u00);
                pa[mt][3] = f2tf32(odd ? u21 : u20);
            }
#pragma unroll
            for (int nf = 0; nf < 8; nf++) {
                uint2 bq = *(uint2*)&Vt[(nf << 3) + u][(kk << 3) + 2 * v];
                uint32_t bf[2] = {bq.x, bq.y};
                MMA_TF32(o[0][nf], pa[0], bf);
                MMA_TF32(o[1][nf], pa[1], bf);
            }
        }
    }

    // ---- epilogue ----
#pragma unroll
    for (int mt = 0; mt < 2; mt++) {
        float inv0 = 1.0f / ll[mt][0], inv1 = 1.0f / ll[mt][1];
        int r0 = W + (mt << 4) + u;
#pragma unroll
        for (int nf = 0; nf < 8; nf++) {
            int cb = (nf << 3) + (v << 1);
            float2 w0 = {o[mt][nf][0] * inv0, o[mt][nf][1] * inv0};
            float2 w1 = {o[mt][nf][2] * inv1, o[mt][nf][3] * inv1};
            *(float2*)(ob + (size_t)r0 * EMB + cb)       = w0;
            *(float2*)(ob + (size_t)(r0 + 8) * EMB + cb) = w1;
        }
    }
}

// ---------------- launch ------------------------------------------------------
extern "C" void kernel_launch(void* const* d_in, const int* in_sizes, int n_in,
                              void* d_out, int out_size) {
    const float* query = (const float*)d_in[0];
    const float* key_  = (const float*)d_in[1];
    const float* value = (const float*)d_in[2];
    const float* wq = (const float*)d_in[3];
    const float* bq = (const float*)d_in[4];
    const float* wk = (const float*)d_in[5];
    const float* bk = (const float*)d_in[6];
    const float* wv = (const float*)d_in[7];
    const float* bv = (const float*)d_in[8];
    const float* wo = (const float*)d_in[9];
    const float* bo = (const float*)d_in[10];
    float* out = (float*)d_out;

    float *qp, *kp, *vp, *vtp, *ap;
    cudaGetSymbolAddress((void**)&qp,  g_q);
    cudaGetSymbolAddress((void**)&kp,  g_k);
    cudaGetSymbolAddress((void**)&vp,  g_v);
    cudaGetSymbolAddress((void**)&vtp, g_vt);
    cudaGetSymbolAddress((void**)&ap,  g_attn);

    cudaFuncSetAttribute(attn_mma_kernel,
                         cudaFuncAttributeMaxDynamicSharedMemorySize, ATT_SMEM);

    build_tables_kernel<<<(SEQL * 32 + 255) / 256, 256>>>();

    const float scaling = 0.125f;    // HD^-0.5
    gemm_qkv_kernel<<<dim3(EMB / 128, MTOT / 128, 3), 256>>>(
        query, key_, value, wq, bq, wk, bk, wv, bv, qp, kp, vp, scaling);

    transpose_v_kernel<<<dim3(SEQL / 32, HD / 32, BSZ * NH), 256>>>(vp, vtp);

    attn_mma_kernel<<<dim3(BSZ * NH, SEQL / 128), 128, ATT_SMEM>>>(qp, kp, vtp, ap);

    gemm_mma_kernel<<<dim3(EMB / 128, MTOT / 128), 256>>>(ap, wo, bo, out, 1.0f);
}